// round 14
// baseline (speedup 1.0000x reference)
#include <cuda_runtime.h>
#include <cuda_bf16.h>
#include <cstdint>

#define MB      4096
#define DMODEL  1024
#define NHEAD   16
#define HDIM    64
#define SEQ     2048
#define FF      4096

// ------------------------- pooled scratch (lifetime-overlaid) ----------------
constexpr size_t MiB = 1024u * 1024u;
__device__ __align__(1024) unsigned char g_pool[136 * MiB];

constexpr size_t OFF_QF  = 0 * MiB;     // fp32 16MB   (phase 2-2.5)
constexpr size_t OFF_KF  = 16 * MiB;
constexpr size_t OFF_VF  = 32 * MiB;
constexpr size_t OFF_O   = 48 * MiB;    // fp32 16MB   (phase 3-4)
constexpr size_t OFF_FF  = 0 * MiB;     // fp32 64MB   (phase 7-8)
constexpr size_t OFF_QQH = 64 * MiB;    // s8 4MB (single-word)
constexpr size_t OFF_KQH = 68 * MiB;
constexpr size_t OFF_VTH = 72 * MiB;    // s8 [bh][HD][S]
constexpr size_t OFF_XQH = 88 * MiB;    // s8 4MB (single-word; phase 1-2)
constexpr size_t OFF_FQH = 64 * MiB;    // s8 16MB each (phase 8-9)
constexpr size_t OFF_FQL = 80 * MiB;
constexpr size_t OFF_T1  = 96 * MiB;    // fp32 16MB   (phase 5-6)
constexpr size_t OFF_Z   = 96 * MiB;    // fp32 16MB   (phase 9-10)
constexpr size_t OFF_Y   = 112 * MiB;   // fp32 16MB   (phase 6-9)
constexpr size_t OFF_OQH = 128 * MiB;   // s8 4MB (single-word; phase 4-5)
constexpr size_t OFF_YQH = 128 * MiB;   // s8 4MB each (phase 6-7; Oq dead)
constexpr size_t OFF_YQL = 132 * MiB;

// quantized transposed weights [N][K] + scales
__device__ __align__(128) signed char g_Wqh_q[DMODEL * DMODEL], g_Wql_q[DMODEL * DMODEL];
__device__ __align__(128) signed char g_Wkh_q[DMODEL * DMODEL], g_Wkl_q[DMODEL * DMODEL];
__device__ __align__(128) signed char g_Wvh_q[DMODEL * DMODEL], g_Wvl_q[DMODEL * DMODEL];
__device__ __align__(128) signed char g_Woh_q[DMODEL * DMODEL], g_Wol_q[DMODEL * DMODEL];
__device__ __align__(128) signed char g_W1h_q[FF * DMODEL],     g_W1l_q[FF * DMODEL];
__device__ __align__(128) signed char g_W2h_q[DMODEL * FF],     g_W2l_q[DMODEL * FF];
__device__ __align__(128) float g_wmax[9216];
__device__ __align__(128) float g_qkvmax[96];   // Q 0..31, K 32..63, V 64..95
__device__ __align__(128) float g_sX [MB];
__device__ __align__(128) float g_sO [MB];
__device__ __align__(128) float g_sy [MB];
__device__ __align__(128) float g_sff[MB];

// ------------------------------ helpers --------------------------------------
__device__ __forceinline__ uint32_t smem_u32(const void* p) {
    uint32_t a;
    asm("{ .reg .u64 t; cvta.to.shared.u64 t, %1; cvt.u32.u64 %0, t; }"
        : "=r"(a) : "l"(p));
    return a;
}
__device__ __forceinline__ void cpasync16(uint32_t s, const void* g) {
    asm volatile("cp.async.cg.shared.global [%0], [%1], 16;"
                 :: "r"(s), "l"(g) : "memory");
}
__device__ __forceinline__ void ldsm4(uint32_t* r, uint32_t addr) {
    asm volatile("ldmatrix.sync.aligned.m8n8.x4.shared.b16 {%0,%1,%2,%3}, [%4];"
        : "=r"(r[0]), "=r"(r[1]), "=r"(r[2]), "=r"(r[3]) : "r"(addr));
}
__device__ __forceinline__ void sts_u16(uint32_t addr, uint32_t v) {
    asm volatile("st.shared.u16 [%0], %1;" :: "r"(addr), "r"(v) : "memory");
}
__device__ __forceinline__ void mma_s8(int* c, const uint32_t* a, const uint32_t* b) {
    asm volatile("mma.sync.aligned.m16n8k32.row.col.s32.s8.s8.s32 "
        "{%0,%1,%2,%3}, {%4,%5,%6,%7}, {%8,%9}, {%0,%1,%2,%3};"
        : "+r"(c[0]), "+r"(c[1]), "+r"(c[2]), "+r"(c[3])
        : "r"(a[0]), "r"(a[1]), "r"(a[2]), "r"(a[3]), "r"(b[0]), "r"(b[1]));
}
__device__ __forceinline__ void q_split(float q, signed char& hi, signed char& lo) {
    int h = __float2int_rn(q);
    int l = __float2int_rn((q - (float)h) * 256.f);
    l = max(-127, min(127, l));
    hi = (signed char)h;
    lo = (signed char)l;
}

// ------------------------- quantization kernels ------------------------------
// SEL 0: X(arg)->Xq single/sX ; SEL 1: O->Oq single/sO ; SEL 2: ff->fq dual/sff
template<int C, int SEL>
__global__ __launch_bounds__(256)
void quant_rows(const float* __restrict__ srcArg)
{
    const float* src;
    signed char *qh, *ql;
    float* smax;
    if constexpr (SEL == 0) {
        src = srcArg;
        qh = (signed char*)(g_pool + OFF_XQH); ql = nullptr;
        smax = g_sX;
    } else if constexpr (SEL == 1) {
        src = (const float*)(g_pool + OFF_O);
        qh = (signed char*)(g_pool + OFF_OQH); ql = nullptr;
        smax = g_sO;
    } else {
        src = (const float*)(g_pool + OFF_FF);
        qh = (signed char*)(g_pool + OFF_FQH); ql = (signed char*)(g_pool + OFF_FQL);
        smax = g_sff;
    }

    __shared__ float red[8];
    __shared__ float bc;
    const int tid = threadIdx.x, row = blockIdx.x;
    constexpr int V = C / 1024;
    const float4* s4 = (const float4*)(src + (size_t)row * C);
    float4 v[V];
    float mx = 0.f;
    #pragma unroll
    for (int i = 0; i < V; i++) {
        v[i] = s4[tid + i * 256];
        mx = fmaxf(mx, fmaxf(fmaxf(fabsf(v[i].x), fabsf(v[i].y)),
                             fmaxf(fabsf(v[i].z), fabsf(v[i].w))));
    }
    #pragma unroll
    for (int o = 16; o >= 1; o >>= 1) mx = fmaxf(mx, __shfl_xor_sync(0xffffffffu, mx, o));
    if ((tid & 31) == 0) red[tid >> 5] = mx;
    __syncthreads();
    if (tid == 0) {
        float t = 1e-20f;
        #pragma unroll
        for (int i = 0; i < 8; i++) t = fmaxf(t, red[i]);
        bc = t; smax[row] = t;
    }
    __syncthreads();
    const float inv = 127.f / bc;
    #pragma unroll
    for (int i = 0; i < V; i++) {
        size_t idx = (size_t)row * C + (tid + i * 256) * 4;
        if constexpr (SEL == 2) {
            char4 h4, l4;
            q_split(v[i].x * inv, h4.x, l4.x);
            q_split(v[i].y * inv, h4.y, l4.y);
            q_split(v[i].z * inv, h4.z, l4.z);
            q_split(v[i].w * inv, h4.w, l4.w);
            *(char4*)(qh + idx) = h4;
            *(char4*)(ql + idx) = l4;
        } else {
            char4 h4;
            h4.x = (signed char)__float2int_rn(v[i].x * inv);
            h4.y = (signed char)__float2int_rn(v[i].y * inv);
            h4.z = (signed char)__float2int_rn(v[i].z * inv);
            h4.w = (signed char)__float2int_rn(v[i].w * inv);
            *(char4*)(qh + idx) = h4;
        }
    }
}

__global__ __launch_bounds__(96)
void zero_scales() { g_qkvmax[threadIdx.x] = 0.f; }

// fused colmax + transpose + dual-word quantize; one CTA per 32 output cols.
// pass 1: colmax over K (DRAM); pass 2: re-read (L2), transpose, quantize.
__global__ __launch_bounds__(256)
void wconv(const float* __restrict__ in, int K, int N, int sel, int moff)
{
    signed char *oh, *ol;
    switch (sel) {
        case 0: oh = g_Wqh_q; ol = g_Wql_q; break;
        case 1: oh = g_Wkh_q; ol = g_Wkl_q; break;
        case 2: oh = g_Wvh_q; ol = g_Wvl_q; break;
        case 3: oh = g_Woh_q; ol = g_Wol_q; break;
        case 4: oh = g_W1h_q; ol = g_W1l_q; break;
        default: oh = g_W2h_q; ol = g_W2l_q; break;
    }
    const bool qkv = sel < 3;
    __shared__ float redm[8][32];
    __shared__ float cmax[32];
    __shared__ float tile[32][33];
    const int tx = threadIdx.x & 31, ty = threadIdx.x >> 5;   // 32 x 8
    const int n0 = blockIdx.x * 32;
    const int n  = n0 + tx;

    // pass 1: column max
    float m = 0.f;
    for (int k = ty; k < K; k += 8) {
        size_t idx = qkv ? ((size_t)(n >> 6) * K * 64 + (size_t)k * 64 + (n & 63))
                         : ((size_t)k * N + n);
        m = fmaxf(m, fabsf(in[idx]));
    }
    redm[ty][tx] = m;
    __syncthreads();
    if (ty == 0) {
        float t = 1e-20f;
        #pragma unroll
        for (int i = 0; i < 8; i++) t = fmaxf(t, redm[i][tx]);
        cmax[tx] = t;
        g_wmax[moff + n] = t;
    }
    __syncthreads();

    // pass 2: transpose-quantize in 32x32 tiles
    for (int k0 = 0; k0 < K; k0 += 32) {
        #pragma unroll
        for (int j = 0; j < 4; j++) {
            int k = k0 + ty + j * 8;
            size_t idx = qkv ? ((size_t)(n >> 6) * K * 64 + (size_t)k * 64 + (n & 63))
                             : ((size_t)k * N + n);
            tile[ty + j * 8][tx] = in[idx];
        }
        __syncthreads();
        #pragma unroll
        for (int j = 0; j < 4; j++) {
            int cl = ty + j * 8;                // column local
            int nn = n0 + cl, k = k0 + tx;
            float inv = 127.f / cmax[cl];
            signed char hi, lo;
            q_split(tile[tx][cl] * inv, hi, lo);
            oh[(size_t)nn * K + k] = hi;
            ol[(size_t)nn * K + k] = lo;
        }
        __syncthreads();
    }
}

// Q and K single-word quant in one launch (blocks [0,4096) = Q, [4096,8192) = K)
__global__ __launch_bounds__(256)
void quant_qk2()
{
    const int sel = (blockIdx.x >= 4096) ? 1 : 0;
    const int blk = blockIdx.x & 4095;
    const float* src = (const float*)(g_pool + (sel == 0 ? OFF_QF : OFF_KF));
    signed char* qh  = (signed char*)(g_pool + (sel == 0 ? OFF_QQH : OFF_KQH));
    int fi = (blk * 256 + threadIdx.x) * 4;
    int bh = fi >> 17;
    float inv = 127.f / g_qkvmax[(sel == 0 ? 0 : 32) + bh];
    float4 v = *(const float4*)(src + fi);
    char4 h4;
    h4.x = (signed char)__float2int_rn(v.x * inv);
    h4.y = (signed char)__float2int_rn(v.y * inv);
    h4.z = (signed char)__float2int_rn(v.z * inv);
    h4.w = (signed char)__float2int_rn(v.w * inv);
    *(char4*)(qh + fi) = h4;
}

// V fp32 [bh][s][hd] -> transposed single-word s8 [bh][hd][s]
__global__ __launch_bounds__(256)
void quant_vt()
{
    __shared__ float tile[32][33];
    const int bh = blockIdx.z;
    const int s0 = blockIdx.x * 32, h0 = blockIdx.y * 32;
    const int tx = threadIdx.x & 31, ty = threadIdx.x >> 5;
    const float* VF = (const float*)(g_pool + OFF_VF) + (size_t)bh * SEQ * HDIM;
    signed char* TH = (signed char*)(g_pool + OFF_VTH) + (size_t)bh * HDIM * SEQ;
    #pragma unroll
    for (int j = 0; j < 4; j++)
        tile[ty + j * 8][tx] = VF[(size_t)(s0 + ty + j * 8) * HDIM + h0 + tx];
    __syncthreads();
    float inv = 127.f / g_qkvmax[64 + bh];
    #pragma unroll
    for (int j = 0; j < 4; j++) {
        int r = ty + j * 8;
        TH[(size_t)(h0 + r) * SEQ + s0 + tx] =
            (signed char)__float2int_rn(tile[tx][r] * inv);
    }
}

// ------------------------------ int8 GEMM ------------------------------------
// LIMBS: 1 (A single x B single), 2 (A single x B dual), 3 (A dual x B dual)
template<int MODE>
__global__ __launch_bounds__(256)
void gemm_i8(const float* __restrict__ bias, const float* __restrict__ resid)
{
    constexpr int KD    = (MODE == 5) ? FF : DMODEL;
    constexpr int NC    = KD / 64;
    constexpr int STG   = 30720;
    constexpr int LIMBS = (MODE <= 2) ? 1 : (MODE == 3) ? 2 : 3;

    extern __shared__ char smraw[];
    const uint32_t sb = smem_u32(smraw);

    const int tid = threadIdx.x, wid = tid >> 5, lane = tid & 31;
    const int wr = wid >> 1, wc = wid & 1;
    const int m0 = blockIdx.y * 128, n0 = blockIdx.x * 64;

    const signed char *Ah, *Al, *Bh, *Bl;
    const float *sAm, *sBm;
    if constexpr (MODE == 0) {
        Ah = (const signed char*)(g_pool + OFF_XQH); Al = nullptr;
        Bh = g_Wqh_q; Bl = nullptr; sAm = g_sX; sBm = g_wmax + 0;
    } else if constexpr (MODE == 1) {
        Ah = (const signed char*)(g_pool + OFF_XQH); Al = nullptr;
        Bh = g_Wkh_q; Bl = nullptr; sAm = g_sX; sBm = g_wmax + 1024;
    } else if constexpr (MODE == 2) {
        Ah = (const signed char*)(g_pool + OFF_XQH); Al = nullptr;
        Bh = g_Wvh_q; Bl = nullptr; sAm = g_sX; sBm = g_wmax + 2048;
    } else if constexpr (MODE == 3) {
        Ah = (const signed char*)(g_pool + OFF_OQH); Al = nullptr;
        Bh = g_Woh_q; Bl = g_Wol_q; sAm = g_sO; sBm = g_wmax + 3072;
    } else if constexpr (MODE == 4) {
        Ah = (const signed char*)(g_pool + OFF_YQH); Al = (const signed char*)(g_pool + OFF_YQL);
        Bh = g_W1h_q; Bl = g_W1l_q; sAm = g_sy; sBm = g_wmax + 5120;
    } else {
        Ah = (const signed char*)(g_pool + OFF_FQH); Al = (const signed char*)(g_pool + OFF_FQL);
        Bh = g_W2h_q; Bl = g_W2l_q; sAm = g_sff; sBm = g_wmax + 4096;
    }

    const signed char* rAh = Ah + (size_t)m0 * KD;
    const signed char* rAl = (LIMBS == 3) ? Al + (size_t)m0 * KD : nullptr;
    const signed char* rBh = Bh + (size_t)n0 * KD;
    const signed char* rBl = (LIMBS >= 2) ? Bl + (size_t)n0 * KD : nullptr;

    const int aldRow = tid >> 1, aldC0 = (tid & 1) * 2;
    const int bldRow = tid >> 2, bldC  = tid & 3;

    auto issue = [&](int k0, int st) {
        uint32_t base = sb + st * STG;
        #pragma unroll
        for (int i = 0; i < 2; i++) {
            int c = aldC0 + i;
            cpasync16(base + aldRow * 80 + c * 16,
                      rAh + (size_t)aldRow * KD + k0 + c * 16);
            if constexpr (LIMBS == 3)
                cpasync16(base + 10240 + aldRow * 80 + c * 16,
                          rAl + (size_t)aldRow * KD + k0 + c * 16);
        }
        cpasync16(base + 20480 + bldRow * 80 + bldC * 16,
                  rBh + (size_t)bldRow * KD + k0 + bldC * 16);
        if constexpr (LIMBS >= 2)
            cpasync16(base + 25600 + bldRow * 80 + bldC * 16,
                      rBl + (size_t)bldRow * KD + k0 + bldC * 16);
        asm volatile("cp.async.commit_group;" ::: "memory");
    };

    int acc1[2][4][4], acc2[2][4][4];
    #pragma unroll
    for (int i = 0; i < 2; i++)
        #pragma unroll
        for (int j = 0; j < 4; j++)
            #pragma unroll
            for (int q = 0; q < 4; q++) { acc1[i][j][q] = 0; acc2[i][j][q] = 0; }

    const int arow = ((lane >> 3) & 1) * 8 + (lane & 7);
    const int achk = lane >> 4;
    const uint32_t aA0 = sb + (uint32_t)(wr * 32 + arow) * 80 + achk * 16;
    const uint32_t bA0 = sb + 20480 + (uint32_t)(wc * 32 + arow) * 80 + achk * 16;

    issue(0, 0);

    for (int ct = 0; ct < NC; ct++) {
        if (ct + 1 < NC) {
            issue((ct + 1) * 64, (ct + 1) & 1);
            asm volatile("cp.async.wait_group 1;" ::: "memory");
        } else {
            asm volatile("cp.async.wait_group 0;" ::: "memory");
        }
        __syncthreads();
        const uint32_t off = (ct & 1) ? (uint32_t)STG : 0u;
        #pragma unroll
        for (int s = 0; s < 2; s++) {
            uint32_t bh[2][4], bl[2][4];
            #pragma unroll
            for (int bj = 0; bj < 2; bj++) {
                uint32_t ba = bA0 + off + bj * (16 * 80) + s * 32;
                ldsm4(bh[bj], ba);
                if constexpr (LIMBS >= 2) ldsm4(bl[bj], ba + 5120);
            }
            #pragma unroll
            for (int mi = 0; mi < 2; mi++) {
                uint32_t ah[4], al[4];
                uint32_t aa = aA0 + off + mi * (16 * 80) + s * 32;
                ldsm4(ah, aa);
                if constexpr (LIMBS == 3) ldsm4(al, aa + 10240);
                #pragma unroll
                for (int nj = 0; nj < 4; nj++) {
                    int bj = nj >> 1, oc = nj & 1;
                    uint32_t bfh[2] = { bh[bj][oc], bh[bj][oc + 2] };
                    mma_s8(acc1[mi][nj], ah, bfh);
                    if constexpr (LIMBS >= 2) {
                        uint32_t bfl[2] = { bl[bj][oc], bl[bj][oc + 2] };
                        mma_s8(acc2[mi][nj], ah, bfl);
                        if constexpr (LIMBS == 3) mma_s8(acc2[mi][nj], al, bfh);
                    }
                }
            }
        }
        __syncthreads();
    }

    const int qrow = lane >> 2, qcol = (lane & 3) * 2;
    const int mrow0 = m0 + wr * 32, ncol0 = n0 + wc * 32;

    float2 bias2[4], sB2[4];
    #pragma unroll
    for (int nj = 0; nj < 4; nj++) {
        int n = ncol0 + nj * 8 + qcol;
        bias2[nj] = *(const float2*)(bias + n);
        sB2[nj]   = *(const float2*)(sBm + n);
    }

    float vmax = 0.f;
    #pragma unroll
    for (int mi = 0; mi < 2; mi++) {
        #pragma unroll
        for (int half = 0; half < 2; half++) {
            int m = mrow0 + mi * 16 + qrow + half * 8;
            float sA = sAm[m] * (1.f / 16129.f);
            #pragma unroll
            for (int nj = 0; nj < 4; nj++) {
                int n = ncol0 + nj * 8 + qcol;
                float r0 = (float)acc1[mi][nj][half * 2 + 0];
                float r1 = (float)acc1[mi][nj][half * 2 + 1];
                if constexpr (LIMBS >= 2) {
                    r0 += (float)acc2[mi][nj][half * 2 + 0] * (1.f / 256.f);
                    r1 += (float)acc2[mi][nj][half * 2 + 1] * (1.f / 256.f);
                }
                float v0 = r0 * sA * sB2[nj].x + bias2[nj].x;
                float v1 = r1 * sA * sB2[nj].y + bias2[nj].y;
                if constexpr (MODE <= 2) {
                    float* outf = (float*)(g_pool +
                        (MODE == 0 ? OFF_QF : MODE == 1 ? OFF_KF : OFF_VF));
                    int b = m >> 11, si = m & 2047, h = n >> 6, e = n & 63;
                    size_t idx = (((size_t)(b * NHEAD + h) * SEQ) + si) * HDIM + e;
                    *(float2*)(outf + idx) = make_float2(v0, v1);
                    vmax = fmaxf(vmax, fmaxf(fabsf(v0), fabsf(v1)));
                } else if constexpr (MODE == 3) {
                    size_t idx = (size_t)m * DMODEL + n;
                    float2 rv = *(const float2*)(resid + idx);
                    *(float2*)((float*)(g_pool + OFF_T1) + idx) = make_float2(v0 + rv.x, v1 + rv.y);
                } else if constexpr (MODE == 4) {
                    size_t idx = (size_t)m * FF + n;
                    *(float2*)((float*)(g_pool + OFF_FF) + idx) =
                        make_float2(fmaxf(v0, 0.f), fmaxf(v1, 0.f));
                } else {
                    size_t idx = (size_t)m * DMODEL + n;
                    float2 rv = *(const float2*)((const float*)(g_pool + OFF_Y) + idx);
                    *(float2*)((float*)(g_pool + OFF_Z) + idx) = make_float2(v0 + rv.x, v1 + rv.y);
                }
            }
        }
    }
    if constexpr (MODE <= 2) {   // fused per-bh absmax (b, h constant per warp tile)
        #pragma unroll
        for (int o = 16; o >= 1; o >>= 1)
            vmax = fmaxf(vmax, __shfl_xor_sync(0xffffffffu, vmax, o));
        if (lane == 0) {
            int b = mrow0 >> 11, h = ncol0 >> 6;
            atomicMax((unsigned int*)&g_qkvmax[MODE * 32 + b * NHEAD + h],
                      __float_as_uint(fmaxf(vmax, 1e-20f)));
        }
    }
}

// ======================= Flash attention (s8; single-word QKV, dual P) =======
// B-fragment pairing for brow/bchk mapping: {f0,f1} rows0-7, {f2,f3} rows8-15.
__global__ __launch_bounds__(128, 4)
void attn_s8()
{
    extern __shared__ char smraw[];
    const uint32_t sb = smem_u32(smraw);
    const int tid = threadIdx.x, lane = tid & 31, w = tid >> 5;
    const int bh = blockIdx.y;
    const int q0 = blockIdx.x * 64;

    const signed char* Qh = (const signed char*)(g_pool + OFF_QQH) + (size_t)bh * SEQ * HDIM;
    const signed char* Kh = (const signed char*)(g_pool + OFF_KQH) + (size_t)bh * SEQ * HDIM;
    const signed char* Th = (const signed char*)(g_pool + OFF_VTH) + (size_t)bh * HDIM * SEQ;

    const float cS = g_qkvmax[bh] * g_qkvmax[32 + bh] * (1.f / (16129.f * 8.f));
    const float cV = g_qkvmax[64 + bh] * (1.f / 16129.f);

    {
        int row = tid >> 1;
        #pragma unroll
        for (int i = 0; i < 2; i++) {
            int c = (tid & 1) * 2 + i;
            cpasync16(sb + row * 80 + c * 16, Qh + (size_t)(q0 + row) * HDIM + c * 16);
        }
    }

    auto kv_issue = [&](int j, int st) {
        uint32_t base = sb + 5120 + st * 10240;
        int row = tid >> 1;
        #pragma unroll
        for (int i = 0; i < 2; i++) {
            int c = (tid & 1) * 2 + i;
            cpasync16(base + row * 80 + c * 16,
                      Kh + (size_t)(j * 64 + row) * HDIM + c * 16);
            cpasync16(base + 5120 + row * 80 + c * 16,
                      Th + (size_t)row * SEQ + j * 64 + c * 16);
        }
        asm volatile("cp.async.commit_group;" ::: "memory");
    };

    kv_issue(0, 0);

    const int arow = ((lane >> 3) & 1) * 8 + (lane & 7);
    const int achk = lane >> 4;
    const int brow = ((lane >> 4) & 1) * 8 + (lane & 7);
    const int bchk = (lane >> 3) & 1;
    const uint32_t qA0 = sb + (uint32_t)(w * 16 + arow) * 80 + achk * 16;
    const uint32_t Pw  = sb + 25600 + (uint32_t)w * 2560;
    const uint32_t pA0 = Pw + (uint32_t)arow * 80 + achk * 16;
    const int r = lane >> 2, cbase = (lane & 3) * 2;

    float acc[8][4];
    #pragma unroll
    for (int j = 0; j < 8; j++)
        #pragma unroll
        for (int q = 0; q < 4; q++) acc[j][q] = 0.f;
    float m0 = -1e30f, m1 = -1e30f, l0 = 0.f, l1 = 0.f;

    for (int jt = 0; jt < SEQ / 64; jt++) {
        if (jt + 1 < SEQ / 64) {
            kv_issue(jt + 1, (jt + 1) & 1);
            asm volatile("cp.async.wait_group 1;" ::: "memory");
        } else {
            asm volatile("cp.async.wait_group 0;" ::: "memory");
        }
        __syncthreads();
        const uint32_t stg = sb + 5120 + (jt & 1) * 10240;

        uint32_t qf[2][4];
        #pragma unroll
        for (int t = 0; t < 2; t++) ldsm4(qf[t], qA0 + t * 32);

        float s[8][4];
        #pragma unroll
        for (int np = 0; np < 4; np++) {
            int a1[2][4] = {{0,0,0,0},{0,0,0,0}};
            #pragma unroll
            for (int t = 0; t < 2; t++) {
                uint32_t kf[4];
                uint32_t ka = stg + (uint32_t)(np * 16 + brow) * 80 + bchk * 16 + t * 32;
                ldsm4(kf, ka);
                uint32_t b0[2] = { kf[0], kf[1] }, b1[2] = { kf[2], kf[3] };
                mma_s8(a1[0], qf[t], b0);
                mma_s8(a1[1], qf[t], b1);
            }
            #pragma unroll
            for (int o = 0; o < 2; o++)
                #pragma unroll
                for (int q = 0; q < 4; q++)
                    s[2 * np + o][q] = cS * (float)a1[o][q];
        }

        float mx0 = -1e30f, mx1 = -1e30f;
        #pragma unroll
        for (int j = 0; j < 8; j++) {
            mx0 = fmaxf(mx0, fmaxf(s[j][0], s[j][1]));
            mx1 = fmaxf(mx1, fmaxf(s[j][2], s[j][3]));
        }
        mx0 = fmaxf(mx0, __shfl_xor_sync(0xffffffffu, mx0, 1));
        mx0 = fmaxf(mx0, __shfl_xor_sync(0xffffffffu, mx0, 2));
        mx1 = fmaxf(mx1, __shfl_xor_sync(0xffffffffu, mx1, 1));
        mx1 = fmaxf(mx1, __shfl_xor_sync(0xffffffffu, mx1, 2));
        float mn0 = fmaxf(m0, mx0), mn1 = fmaxf(m1, mx1);
        float cr0 = __expf(m0 - mn0), cr1 = __expf(m1 - mn1);
        float sum0 = 0.f, sum1 = 0.f;
        #pragma unroll
        for (int j = 0; j < 8; j++) {
            s[j][0] = __expf(s[j][0] - mn0); sum0 += s[j][0];
            s[j][1] = __expf(s[j][1] - mn0); sum0 += s[j][1];
            s[j][2] = __expf(s[j][2] - mn1); sum1 += s[j][2];
            s[j][3] = __expf(s[j][3] - mn1); sum1 += s[j][3];
        }
        sum0 += __shfl_xor_sync(0xffffffffu, sum0, 1);
        sum0 += __shfl_xor_sync(0xffffffffu, sum0, 2);
        sum1 += __shfl_xor_sync(0xffffffffu, sum1, 1);
        sum1 += __shfl_xor_sync(0xffffffffu, sum1, 2);
        l0 = l0 * cr0 + sum0;  m0 = mn0;
        l1 = l1 * cr1 + sum1;  m1 = mn1;
        #pragma unroll
        for (int j = 0; j < 8; j++) {
            acc[j][0] *= cr0; acc[j][1] *= cr0;
            acc[j][2] *= cr1; acc[j][3] *= cr1;
        }

        #pragma unroll
        for (int j = 0; j < 8; j++) {
            int h0i = __float2int_rn(s[j][0] * 127.f);
            int l0i = min(127, max(-127, __float2int_rn((s[j][0] * 127.f - h0i) * 256.f)));
            int h1i = __float2int_rn(s[j][1] * 127.f);
            int l1i = min(127, max(-127, __float2int_rn((s[j][1] * 127.f - h1i) * 256.f)));
            int h2i = __float2int_rn(s[j][2] * 127.f);
            int l2i = min(127, max(-127, __float2int_rn((s[j][2] * 127.f - h2i) * 256.f)));
            int h3i = __float2int_rn(s[j][3] * 127.f);
            int l3i = min(127, max(-127, __float2int_rn((s[j][3] * 127.f - h3i) * 256.f)));
            uint32_t col = 8 * j + cbase;
            sts_u16(Pw + r * 80 + col,          (h0i & 0xFF) | ((h1i & 0xFF) << 8));
            sts_u16(Pw + 1280 + r * 80 + col,   (l0i & 0xFF) | ((l1i & 0xFF) << 8));
            sts_u16(Pw + (r + 8) * 80 + col,        (h2i & 0xFF) | ((h3i & 0xFF) << 8));
            sts_u16(Pw + 1280 + (r + 8) * 80 + col, (l2i & 0xFF) | ((l3i & 0xFF) << 8));
        }
        __syncwarp();

        uint32_t pfh[2][4], pfl[2][4];
        #pragma unroll
        for (int t = 0; t < 2; t++) {
            ldsm4(pfh[t], pA0 + t * 32);
            ldsm4(pfl[t], pA0 + 1280 + t * 32);
        }

        #pragma unroll
        for (int np = 0; np < 4; np++) {
            int a1[2][4] = {{0,0,0,0},{0,0,0,0}};
            int a2[2][4] = {{0,0,0,0},{0,0,0,0}};
            #pragma unroll
            for (int t = 0; t < 2; t++) {
                uint32_t vf[4];
                uint32_t va = stg + 5120 + (uint32_t)(np * 16 + brow) * 80 + bchk * 16 + t * 32;
                ldsm4(vf, va);
                uint32_t b0[2] = { vf[0], vf[1] }, b1[2] = { vf[2], vf[3] };
                mma_s8(a1[0], pfh[t], b0); mma_s8(a2[0], pfl[t], b0);
                mma_s8(a1[1], pfh[t], b1); mma_s8(a2[1], pfl[t], b1);
            }
            #pragma unroll
            for (int o = 0; o < 2; o++)
                #pragma unroll
                for (int q = 0; q < 4; q++)
                    acc[2 * np + o][q] += (float)a1[o][q] + (float)a2[o][q] * (1.f / 256.f);
        }
        __syncthreads();
    }

    const int b = bh >> 4, h = bh & 15;
    const float inv0 = cV / l0, inv1 = cV / l1;
    const int row0 = q0 + w * 16 + r;
    float* OB = (float*)(g_pool + OFF_O) + ((size_t)b * SEQ) * DMODEL + (size_t)h * HDIM;
    #pragma unroll
    for (int j = 0; j < 8; j++) {
        int col = 8 * j + cbase;
        *(float2*)(OB + (size_t)row0 * DMODEL + col) =
            make_float2(acc[j][0] * inv0, acc[j][1] * inv0);
        *(float2*)(OB + (size_t)(row0 + 8) * DMODEL + col) =
            make_float2(acc[j][2] * inv1, acc[j][3] * inv1);
    }
}

// =============================== LayerNorm ===================================
__global__ __launch_bounds__(256)
void ln_kernel(const float* __restrict__ g, const float* __restrict__ b,
               float* __restrict__ dstArg, int which)
{
    __shared__ float red[8];
    __shared__ float bc;
    const int tid = threadIdx.x;
    const int row = blockIdx.x;
    const float* src = (which == 0) ? (const float*)(g_pool + OFF_T1)
                                    : (const float*)(g_pool + OFF_Z);
    float* dst = (which == 0) ? (float*)(g_pool + OFF_Y) : dstArg;

    float4 v = ((const float4*)(src + (size_t)row * DMODEL))[tid];
    float s = v.x + v.y + v.z + v.w;
    #pragma unroll
    for (int o = 16; o >= 1; o >>= 1) s += __shfl_xor_sync(0xffffffffu, s, o);
    if ((tid & 31) == 0) red[tid >> 5] = s;
    __syncthreads();
    if (tid == 0) {
        float t = 0.f;
        #pragma unroll
        for (int i = 0; i < 8; i++) t += red[i];
        bc = t;
    }
    __syncthreads();
    float mu = bc * (1.f / DMODEL);
    float dx = v.x - mu, dy = v.y - mu, dz = v.z - mu, dw = v.w - mu;
    float s2 = dx * dx + dy * dy + dz * dz + dw * dw;
    #pragma unroll
    for (int o = 16; o >= 1; o >>= 1) s2 += __shfl_xor_sync(0xffffffffu, s2, o);
    __syncthreads();
    if ((tid & 31) == 0) red[tid >> 5] = s2;
    __syncthreads();
    if (tid == 0) {
        float t = 0.f;
        #pragma unroll
        for (int i = 0; i < 8; i++) t += red[i];
        bc = t;
    }
    __syncthreads();
    float rstd = rsqrtf(bc * (1.f / DMODEL) + 1e-5f);
    float4 gg = ((const float4*)g)[tid];
    float4 bb = ((const float4*)b)[tid];
    float4 o4;
    o4.x = dx * rstd * gg.x + bb.x;
    o4.y = dy * rstd * gg.y + bb.y;
    o4.z = dz * rstd * gg.z + bb.z;
    o4.w = dw * rstd * gg.w + bb.w;
    ((float4*)(dst + (size_t)row * DMODEL))[tid] = o4;

    if (which == 0) {
        float am = fmaxf(fmaxf(fabsf(o4.x), fabsf(o4.y)), fmaxf(fabsf(o4.z), fabsf(o4.w)));
        #pragma unroll
        for (int o = 16; o >= 1; o >>= 1) am = fmaxf(am, __shfl_xor_sync(0xffffffffu, am, o));
        __syncthreads();
        if ((tid & 31) == 0) red[tid >> 5] = am;
        __syncthreads();
        if (tid == 0) {
            float t = 1e-20f;
            #pragma unroll
            for (int i = 0; i < 8; i++) t = fmaxf(t, red[i]);
            bc = t; g_sy[row] = t;
        }
        __syncthreads();
        float inv = 127.f / bc;
        char4 h4, l4;
        q_split(o4.x * inv, h4.x, l4.x);
        q_split(o4.y * inv, h4.y, l4.y);
        q_split(o4.z * inv, h4.z, l4.z);
        q_split(o4.w * inv, h4.w, l4.w);
        size_t idx = (size_t)row * DMODEL + tid * 4;
        *(char4*)((signed char*)(g_pool + OFF_YQH) + idx) = h4;
        *(char4*)((signed char*)(g_pool + OFF_YQL) + idx) = l4;
    }
}

// ================================ launch =====================================
extern "C" void kernel_launch(void* const* d_in, const int* in_sizes, int n_in,
                              void* d_out, int out_size)
{
    (void)in_sizes; (void)n_in; (void)out_size;
    const float* X   = (const float*)d_in[0];
    const float* Wq  = (const float*)d_in[1];
    const float* bq  = (const float*)d_in[2];
    const float* Wk  = (const float*)d_in[3];
    const float* bk  = (const float*)d_in[4];
    const float* Wv  = (const float*)d_in[5];
    const float* bv  = (const float*)d_in[6];
    const float* Wo  = (const float*)d_in[7];
    const float* bo  = (const float*)d_in[8];
    const float* l1g = (const float*)d_in[9];
    const float* l1b = (const float*)d_in[10];
    const float* W1  = (const float*)d_in[11];
    const float* b1  = (const float*)d_in[12];
    const float* W2  = (const float*)d_in[13];
    const float* b2  = (const float*)d_in[14];
    const float* l2g = (const float*)d_in[15];
    const float* l2b = (const float*)d_in[16];

    const int g8_smem = 2 * 30720;
    cudaFuncSetAttribute(gemm_i8<0>, cudaFuncAttributeMaxDynamicSharedMemorySize, g8_smem);
    cudaFuncSetAttribute(gemm_i8<1>, cudaFuncAttributeMaxDynamicSharedMemorySize, g8_smem);
    cudaFuncSetAttribute(gemm_i8<2>, cudaFuncAttributeMaxDynamicSharedMemorySize, g8_smem);
    cudaFuncSetAttribute(gemm_i8<3>, cudaFuncAttributeMaxDynamicSharedMemorySize, g8_smem);
    cudaFuncSetAttribute(gemm_i8<4>, cudaFuncAttributeMaxDynamicSharedMemorySize, g8_smem);
    cudaFuncSetAttribute(gemm_i8<5>, cudaFuncAttributeMaxDynamicSharedMemorySize, g8_smem);
    const int attn_smem = 35840;
    cudaFuncSetAttribute(attn_s8, cudaFuncAttributeMaxDynamicSharedMemorySize, attn_smem);

    dim3 thr(256);

    zero_scales<<<1, 96>>>();
    quant_rows<1024, 0><<<MB, thr>>>(X);
    wconv<<<32,  thr>>>(Wq, 1024, 1024, 0, 0);
    wconv<<<32,  thr>>>(Wk, 1024, 1024, 1, 1024);
    wconv<<<32,  thr>>>(Wv, 1024, 1024, 2, 2048);
    wconv<<<32,  thr>>>(Wo, 1024, 1024, 3, 3072);
    wconv<<<128, thr>>>(W1, 1024, 4096, 4, 5120);
    wconv<<<32,  thr>>>(W2, 4096, 1024, 5, 4096);

    // QKV projections (1-limb) with fused per-bh absmax
    gemm_i8<0><<<dim3(16, 32), thr, g8_smem>>>(bq, nullptr);
    gemm_i8<1><<<dim3(16, 32), thr, g8_smem>>>(bk, nullptr);
    gemm_i8<2><<<dim3(16, 32), thr, g8_smem>>>(bv, nullptr);

    quant_qk2<<<8192, thr>>>();
    quant_vt<<<dim3(64, 2, 32), thr>>>();

    attn_s8<<<dim3(32, 32), dim3(128), attn_smem>>>();

    quant_rows<1024, 1><<<MB, thr>>>(nullptr);
    gemm_i8<3><<<dim3(16, 32), thr, g8_smem>>>(bo, X);
    ln_kernel<<<MB, thr>>>(l1g, l1b, nullptr, 0);

    gemm_i8<4><<<dim3(64, 32), thr, g8_smem>>>(b1, nullptr);
    quant_rows<4096, 2><<<MB, thr>>>(nullptr);
    gemm_i8<5><<<dim3(16, 32), thr, g8_smem>>>(b2, nullptr);
    ln_kernel<<<MB, thr>>>(l2g, l2b, (float*)d_out, 1);
}

// round 15
// speedup vs baseline: 1.1817x; 1.1817x over previous
#include <cuda_runtime.h>
#include <cuda_bf16.h>
#include <cstdint>

#define MB      4096
#define DMODEL  1024
#define NHEAD   16
#define HDIM    64
#define SEQ     2048
#define FF      4096

// ------------------------- pooled scratch (lifetime-overlaid) ----------------
constexpr size_t MiB = 1024u * 1024u;
__device__ __align__(1024) unsigned char g_pool[136 * MiB];

constexpr size_t OFF_QF  = 0 * MiB;     // fp32 16MB   (phase 2-2.5)
constexpr size_t OFF_KF  = 16 * MiB;
constexpr size_t OFF_VF  = 32 * MiB;
constexpr size_t OFF_O   = 48 * MiB;    // fp32 16MB   (phase 3-4)
constexpr size_t OFF_FF  = 0 * MiB;     // fp32 64MB   (phase 7-8)
constexpr size_t OFF_QQH = 64 * MiB;    // s8 4MB (single-word)
constexpr size_t OFF_KQH = 68 * MiB;
constexpr size_t OFF_VTH = 72 * MiB;    // s8 [bh][HD][S]
constexpr size_t OFF_XQH = 88 * MiB;    // s8 4MB (single-word; phase 1-2)
constexpr size_t OFF_FQH = 64 * MiB;    // s8 16MB each (phase 8-9)
constexpr size_t OFF_FQL = 80 * MiB;
constexpr size_t OFF_T1  = 96 * MiB;    // fp32 16MB   (phase 5-6)
constexpr size_t OFF_Z   = 96 * MiB;    // fp32 16MB   (phase 9-10)
constexpr size_t OFF_Y   = 112 * MiB;   // fp32 16MB   (phase 6-9)
constexpr size_t OFF_OQH = 128 * MiB;   // s8 4MB (single-word; phase 4-5)
constexpr size_t OFF_YQH = 128 * MiB;   // s8 4MB each (phase 6-7; Oq dead)
constexpr size_t OFF_YQL = 132 * MiB;

// quantized transposed weights [N][K] + scales
__device__ __align__(128) signed char g_Wqh_q[DMODEL * DMODEL], g_Wql_q[DMODEL * DMODEL];
__device__ __align__(128) signed char g_Wkh_q[DMODEL * DMODEL], g_Wkl_q[DMODEL * DMODEL];
__device__ __align__(128) signed char g_Wvh_q[DMODEL * DMODEL], g_Wvl_q[DMODEL * DMODEL];
__device__ __align__(128) signed char g_Woh_q[DMODEL * DMODEL], g_Wol_q[DMODEL * DMODEL];
__device__ __align__(128) signed char g_W1h_q[FF * DMODEL],     g_W1l_q[FF * DMODEL];
__device__ __align__(128) signed char g_W2h_q[DMODEL * FF],     g_W2l_q[DMODEL * FF];
__device__ __align__(128) float g_wmax[9216];
__device__ __align__(128) float g_qkvmax[96];   // Q 0..31, K 32..63, V 64..95
__device__ __align__(128) float g_sX [MB];
__device__ __align__(128) float g_sO [MB];
__device__ __align__(128) float g_sy [MB];
__device__ __align__(128) float g_sff[MB];

// ------------------------------ helpers --------------------------------------
__device__ __forceinline__ uint32_t smem_u32(const void* p) {
    uint32_t a;
    asm("{ .reg .u64 t; cvta.to.shared.u64 t, %1; cvt.u32.u64 %0, t; }"
        : "=r"(a) : "l"(p));
    return a;
}
__device__ __forceinline__ void cpasync16(uint32_t s, const void* g) {
    asm volatile("cp.async.cg.shared.global [%0], [%1], 16;"
                 :: "r"(s), "l"(g) : "memory");
}
__device__ __forceinline__ void ldsm4(uint32_t* r, uint32_t addr) {
    asm volatile("ldmatrix.sync.aligned.m8n8.x4.shared.b16 {%0,%1,%2,%3}, [%4];"
        : "=r"(r[0]), "=r"(r[1]), "=r"(r[2]), "=r"(r[3]) : "r"(addr));
}
__device__ __forceinline__ void sts_u16(uint32_t addr, uint32_t v) {
    asm volatile("st.shared.u16 [%0], %1;" :: "r"(addr), "r"(v) : "memory");
}
__device__ __forceinline__ void mma_s8(int* c, const uint32_t* a, const uint32_t* b) {
    asm volatile("mma.sync.aligned.m16n8k32.row.col.s32.s8.s8.s32 "
        "{%0,%1,%2,%3}, {%4,%5,%6,%7}, {%8,%9}, {%0,%1,%2,%3};"
        : "+r"(c[0]), "+r"(c[1]), "+r"(c[2]), "+r"(c[3])
        : "r"(a[0]), "r"(a[1]), "r"(a[2]), "r"(a[3]), "r"(b[0]), "r"(b[1]));
}
__device__ __forceinline__ void q_split(float q, signed char& hi, signed char& lo) {
    int h = __float2int_rn(q);
    int l = __float2int_rn((q - (float)h) * 256.f);
    l = max(-127, min(127, l));
    hi = (signed char)h;
    lo = (signed char)l;
}

// ------------------------- quantization kernels ------------------------------
// SEL 0: X(arg)->Xq single/sX ; SEL 1: O->Oq single/sO ; SEL 2: ff->fq dual/sff
template<int C, int SEL>
__global__ __launch_bounds__(256)
void quant_rows(const float* __restrict__ srcArg)
{
    const float* src;
    signed char *qh, *ql;
    float* smax;
    if constexpr (SEL == 0) {
        src = srcArg;
        qh = (signed char*)(g_pool + OFF_XQH); ql = nullptr;
        smax = g_sX;
    } else if constexpr (SEL == 1) {
        src = (const float*)(g_pool + OFF_O);
        qh = (signed char*)(g_pool + OFF_OQH); ql = nullptr;
        smax = g_sO;
    } else {
        src = (const float*)(g_pool + OFF_FF);
        qh = (signed char*)(g_pool + OFF_FQH); ql = (signed char*)(g_pool + OFF_FQL);
        smax = g_sff;
    }

    __shared__ float red[8];
    __shared__ float bc;
    const int tid = threadIdx.x, row = blockIdx.x;
    constexpr int V = C / 1024;
    const float4* s4 = (const float4*)(src + (size_t)row * C);
    float4 v[V];
    float mx = 0.f;
    #pragma unroll
    for (int i = 0; i < V; i++) {
        v[i] = s4[tid + i * 256];
        mx = fmaxf(mx, fmaxf(fmaxf(fabsf(v[i].x), fabsf(v[i].y)),
                             fmaxf(fabsf(v[i].z), fabsf(v[i].w))));
    }
    #pragma unroll
    for (int o = 16; o >= 1; o >>= 1) mx = fmaxf(mx, __shfl_xor_sync(0xffffffffu, mx, o));
    if ((tid & 31) == 0) red[tid >> 5] = mx;
    __syncthreads();
    if (tid == 0) {
        float t = 1e-20f;
        #pragma unroll
        for (int i = 0; i < 8; i++) t = fmaxf(t, red[i]);
        bc = t; smax[row] = t;
    }
    __syncthreads();
    const float inv = 127.f / bc;
    #pragma unroll
    for (int i = 0; i < V; i++) {
        size_t idx = (size_t)row * C + (tid + i * 256) * 4;
        if constexpr (SEL == 2) {
            char4 h4, l4;
            q_split(v[i].x * inv, h4.x, l4.x);
            q_split(v[i].y * inv, h4.y, l4.y);
            q_split(v[i].z * inv, h4.z, l4.z);
            q_split(v[i].w * inv, h4.w, l4.w);
            *(char4*)(qh + idx) = h4;
            *(char4*)(ql + idx) = l4;
        } else {
            char4 h4;
            h4.x = (signed char)__float2int_rn(v[i].x * inv);
            h4.y = (signed char)__float2int_rn(v[i].y * inv);
            h4.z = (signed char)__float2int_rn(v[i].z * inv);
            h4.w = (signed char)__float2int_rn(v[i].w * inv);
            *(char4*)(qh + idx) = h4;
        }
    }
}

__global__ __launch_bounds__(256)
void zero_scales() {
    int i = blockIdx.x * 256 + threadIdx.x;
    if (i < 9216) g_wmax[i] = 0.f;
    if (i < 96)   g_qkvmax[i] = 0.f;
}

__global__ __launch_bounds__(256)
void wcolmax(const float* __restrict__ w, int K, int N, int qkv, int moff)
{
    int n = blockIdx.x * 256 + threadIdx.x;
    int kspan = K / 32;
    int k0 = blockIdx.y * kspan;
    float m = 0.f;
    for (int k = k0; k < k0 + kspan; k++) {
        size_t idx = qkv ? ((size_t)(n >> 6) * K * 64 + (size_t)k * 64 + (n & 63))
                         : ((size_t)k * N + n);
        m = fmaxf(m, fabsf(w[idx]));
    }
    atomicMax((unsigned int*)&g_wmax[moff + n], __float_as_uint(m));
}

__global__ __launch_bounds__(256)
void conv_wq(const float* __restrict__ in, int K, int N, int sel, int moff)
{
    signed char *oh, *ol;
    switch (sel) {
        case 0: oh = g_Wqh_q; ol = g_Wql_q; break;
        case 1: oh = g_Wkh_q; ol = g_Wkl_q; break;
        case 2: oh = g_Wvh_q; ol = g_Wvl_q; break;
        case 3: oh = g_Woh_q; ol = g_Wol_q; break;
        case 4: oh = g_W1h_q; ol = g_W1l_q; break;
        default: oh = g_W2h_q; ol = g_W2l_q; break;
    }
    const bool qkv = sel < 3;
    __shared__ float tile[32][33];
    int tx = threadIdx.x & 31, ty = threadIdx.x >> 5;
    int n0 = blockIdx.x * 32, k0 = blockIdx.y * 32;
    #pragma unroll
    for (int j = 0; j < 4; j++) {
        int k = k0 + ty + j * 8, n = n0 + tx;
        size_t idx = qkv ? ((size_t)(n >> 6) * K * 64 + (size_t)k * 64 + (n & 63))
                         : ((size_t)k * N + n);
        tile[ty + j * 8][tx] = in[idx];
    }
    __syncthreads();
    #pragma unroll
    for (int j = 0; j < 4; j++) {
        int n = n0 + ty + j * 8, k = k0 + tx;
        float inv = 127.f / fmaxf(g_wmax[moff + n], 1e-20f);
        signed char hi, lo;
        q_split(tile[tx][ty + j * 8] * inv, hi, lo);
        oh[(size_t)n * K + k] = hi;
        ol[(size_t)n * K + k] = lo;
    }
}

// Q and K single-word quant in one launch (blocks [0,4096) = Q, [4096,8192) = K)
__global__ __launch_bounds__(256)
void quant_qk2()
{
    const int sel = (blockIdx.x >= 4096) ? 1 : 0;
    const int blk = blockIdx.x & 4095;
    const float* src = (const float*)(g_pool + (sel == 0 ? OFF_QF : OFF_KF));
    signed char* qh  = (signed char*)(g_pool + (sel == 0 ? OFF_QQH : OFF_KQH));
    int fi = (blk * 256 + threadIdx.x) * 4;
    int bh = fi >> 17;
    float inv = 127.f / g_qkvmax[(sel == 0 ? 0 : 32) + bh];
    float4 v = *(const float4*)(src + fi);
    char4 h4;
    h4.x = (signed char)__float2int_rn(v.x * inv);
    h4.y = (signed char)__float2int_rn(v.y * inv);
    h4.z = (signed char)__float2int_rn(v.z * inv);
    h4.w = (signed char)__float2int_rn(v.w * inv);
    *(char4*)(qh + fi) = h4;
}

// V fp32 [bh][s][hd] -> transposed single-word s8 [bh][hd][s]
__global__ __launch_bounds__(256)
void quant_vt()
{
    __shared__ float tile[32][33];
    const int bh = blockIdx.z;
    const int s0 = blockIdx.x * 32, h0 = blockIdx.y * 32;
    const int tx = threadIdx.x & 31, ty = threadIdx.x >> 5;
    const float* VF = (const float*)(g_pool + OFF_VF) + (size_t)bh * SEQ * HDIM;
    signed char* TH = (signed char*)(g_pool + OFF_VTH) + (size_t)bh * HDIM * SEQ;
    #pragma unroll
    for (int j = 0; j < 4; j++)
        tile[ty + j * 8][tx] = VF[(size_t)(s0 + ty + j * 8) * HDIM + h0 + tx];
    __syncthreads();
    float inv = 127.f / g_qkvmax[64 + bh];
    #pragma unroll
    for (int j = 0; j < 4; j++) {
        int r = ty + j * 8;
        TH[(size_t)(h0 + r) * SEQ + s0 + tx] =
            (signed char)__float2int_rn(tile[tx][r] * inv);
    }
}

// ------------------------------ int8 GEMM ------------------------------------
// LIMBS: 1 (A single x B single), 2 (A single x B dual), 3 (A dual x B dual)
template<int MODE>
__global__ __launch_bounds__(256)
void gemm_i8(const float* __restrict__ bias, const float* __restrict__ resid)
{
    constexpr int KD    = (MODE == 5) ? FF : DMODEL;
    constexpr int NC    = KD / 64;
    constexpr int STG   = 30720;
    constexpr int LIMBS = (MODE <= 2) ? 1 : (MODE == 3) ? 2 : 3;

    extern __shared__ char smraw[];
    const uint32_t sb = smem_u32(smraw);

    const int tid = threadIdx.x, wid = tid >> 5, lane = tid & 31;
    const int wr = wid >> 1, wc = wid & 1;
    const int m0 = blockIdx.y * 128, n0 = blockIdx.x * 64;

    const signed char *Ah, *Al, *Bh, *Bl;
    const float *sAm, *sBm;
    if constexpr (MODE == 0) {
        Ah = (const signed char*)(g_pool + OFF_XQH); Al = nullptr;
        Bh = g_Wqh_q; Bl = nullptr; sAm = g_sX; sBm = g_wmax + 0;
    } else if constexpr (MODE == 1) {
        Ah = (const signed char*)(g_pool + OFF_XQH); Al = nullptr;
        Bh = g_Wkh_q; Bl = nullptr; sAm = g_sX; sBm = g_wmax + 1024;
    } else if constexpr (MODE == 2) {
        Ah = (const signed char*)(g_pool + OFF_XQH); Al = nullptr;
        Bh = g_Wvh_q; Bl = nullptr; sAm = g_sX; sBm = g_wmax + 2048;
    } else if constexpr (MODE == 3) {
        Ah = (const signed char*)(g_pool + OFF_OQH); Al = nullptr;
        Bh = g_Woh_q; Bl = g_Wol_q; sAm = g_sO; sBm = g_wmax + 3072;
    } else if constexpr (MODE == 4) {
        Ah = (const signed char*)(g_pool + OFF_YQH); Al = (const signed char*)(g_pool + OFF_YQL);
        Bh = g_W1h_q; Bl = g_W1l_q; sAm = g_sy; sBm = g_wmax + 5120;
    } else {
        Ah = (const signed char*)(g_pool + OFF_FQH); Al = (const signed char*)(g_pool + OFF_FQL);
        Bh = g_W2h_q; Bl = g_W2l_q; sAm = g_sff; sBm = g_wmax + 4096;
    }

    const signed char* rAh = Ah + (size_t)m0 * KD;
    const signed char* rAl = (LIMBS == 3) ? Al + (size_t)m0 * KD : nullptr;
    const signed char* rBh = Bh + (size_t)n0 * KD;
    const signed char* rBl = (LIMBS >= 2) ? Bl + (size_t)n0 * KD : nullptr;

    const int aldRow = tid >> 1, aldC0 = (tid & 1) * 2;
    const int bldRow = tid >> 2, bldC  = tid & 3;

    auto issue = [&](int k0, int st) {
        uint32_t base = sb + st * STG;
        #pragma unroll
        for (int i = 0; i < 2; i++) {
            int c = aldC0 + i;
            cpasync16(base + aldRow * 80 + c * 16,
                      rAh + (size_t)aldRow * KD + k0 + c * 16);
            if constexpr (LIMBS == 3)
                cpasync16(base + 10240 + aldRow * 80 + c * 16,
                          rAl + (size_t)aldRow * KD + k0 + c * 16);
        }
        cpasync16(base + 20480 + bldRow * 80 + bldC * 16,
                  rBh + (size_t)bldRow * KD + k0 + bldC * 16);
        if constexpr (LIMBS >= 2)
            cpasync16(base + 25600 + bldRow * 80 + bldC * 16,
                      rBl + (size_t)bldRow * KD + k0 + bldC * 16);
        asm volatile("cp.async.commit_group;" ::: "memory");
    };

    int acc1[2][4][4], acc2[2][4][4];
    #pragma unroll
    for (int i = 0; i < 2; i++)
        #pragma unroll
        for (int j = 0; j < 4; j++)
            #pragma unroll
            for (int q = 0; q < 4; q++) { acc1[i][j][q] = 0; acc2[i][j][q] = 0; }

    const int arow = ((lane >> 3) & 1) * 8 + (lane & 7);
    const int achk = lane >> 4;
    const uint32_t aA0 = sb + (uint32_t)(wr * 32 + arow) * 80 + achk * 16;
    const uint32_t bA0 = sb + 20480 + (uint32_t)(wc * 32 + arow) * 80 + achk * 16;

    issue(0, 0);

    for (int ct = 0; ct < NC; ct++) {
        if (ct + 1 < NC) {
            issue((ct + 1) * 64, (ct + 1) & 1);
            asm volatile("cp.async.wait_group 1;" ::: "memory");
        } else {
            asm volatile("cp.async.wait_group 0;" ::: "memory");
        }
        __syncthreads();
        const uint32_t off = (ct & 1) ? (uint32_t)STG : 0u;
        #pragma unroll
        for (int s = 0; s < 2; s++) {
            uint32_t bh[2][4], bl[2][4];
            #pragma unroll
            for (int bj = 0; bj < 2; bj++) {
                uint32_t ba = bA0 + off + bj * (16 * 80) + s * 32;
                ldsm4(bh[bj], ba);
                if constexpr (LIMBS >= 2) ldsm4(bl[bj], ba + 5120);
            }
            #pragma unroll
            for (int mi = 0; mi < 2; mi++) {
                uint32_t ah[4], al[4];
                uint32_t aa = aA0 + off + mi * (16 * 80) + s * 32;
                ldsm4(ah, aa);
                if constexpr (LIMBS == 3) ldsm4(al, aa + 10240);
                #pragma unroll
                for (int nj = 0; nj < 4; nj++) {
                    int bj = nj >> 1, oc = nj & 1;
                    uint32_t bfh[2] = { bh[bj][oc], bh[bj][oc + 2] };
                    mma_s8(acc1[mi][nj], ah, bfh);
                    if constexpr (LIMBS >= 2) {
                        uint32_t bfl[2] = { bl[bj][oc], bl[bj][oc + 2] };
                        mma_s8(acc2[mi][nj], ah, bfl);
                        if constexpr (LIMBS == 3) mma_s8(acc2[mi][nj], al, bfh);
                    }
                }
            }
        }
        __syncthreads();
    }

    const int qrow = lane >> 2, qcol = (lane & 3) * 2;
    const int mrow0 = m0 + wr * 32, ncol0 = n0 + wc * 32;

    float2 bias2[4], sB2[4];
    #pragma unroll
    for (int nj = 0; nj < 4; nj++) {
        int n = ncol0 + nj * 8 + qcol;
        bias2[nj] = *(const float2*)(bias + n);
        sB2[nj]   = *(const float2*)(sBm + n);
    }

    float vmax = 0.f;
    #pragma unroll
    for (int mi = 0; mi < 2; mi++) {
        #pragma unroll
        for (int half = 0; half < 2; half++) {
            int m = mrow0 + mi * 16 + qrow + half * 8;
            float sA = sAm[m] * (1.f / 16129.f);
            #pragma unroll
            for (int nj = 0; nj < 4; nj++) {
                int n = ncol0 + nj * 8 + qcol;
                float r0 = (float)acc1[mi][nj][half * 2 + 0];
                float r1 = (float)acc1[mi][nj][half * 2 + 1];
                if constexpr (LIMBS >= 2) {
                    r0 += (float)acc2[mi][nj][half * 2 + 0] * (1.f / 256.f);
                    r1 += (float)acc2[mi][nj][half * 2 + 1] * (1.f / 256.f);
                }
                float v0 = r0 * sA * sB2[nj].x + bias2[nj].x;
                float v1 = r1 * sA * sB2[nj].y + bias2[nj].y;
                if constexpr (MODE <= 2) {
                    float* outf = (float*)(g_pool +
                        (MODE == 0 ? OFF_QF : MODE == 1 ? OFF_KF : OFF_VF));
                    int b = m >> 11, si = m & 2047, h = n >> 6, e = n & 63;
                    size_t idx = (((size_t)(b * NHEAD + h) * SEQ) + si) * HDIM + e;
                    *(float2*)(outf + idx) = make_float2(v0, v1);
                    vmax = fmaxf(vmax, fmaxf(fabsf(v0), fabsf(v1)));
                } else if constexpr (MODE == 3) {
                    size_t idx = (size_t)m * DMODEL + n;
                    float2 rv = *(const float2*)(resid + idx);
                    *(float2*)((float*)(g_pool + OFF_T1) + idx) = make_float2(v0 + rv.x, v1 + rv.y);
                } else if constexpr (MODE == 4) {
                    size_t idx = (size_t)m * FF + n;
                    *(float2*)((float*)(g_pool + OFF_FF) + idx) =
                        make_float2(fmaxf(v0, 0.f), fmaxf(v1, 0.f));
                } else {
                    size_t idx = (size_t)m * DMODEL + n;
                    float2 rv = *(const float2*)((const float*)(g_pool + OFF_Y) + idx);
                    *(float2*)((float*)(g_pool + OFF_Z) + idx) = make_float2(v0 + rv.x, v1 + rv.y);
                }
            }
        }
    }
    if constexpr (MODE <= 2) {   // fused per-bh absmax (b, h constant per warp tile)
        #pragma unroll
        for (int o = 16; o >= 1; o >>= 1)
            vmax = fmaxf(vmax, __shfl_xor_sync(0xffffffffu, vmax, o));
        if (lane == 0) {
            int b = mrow0 >> 11, h = ncol0 >> 6;
            atomicMax((unsigned int*)&g_qkvmax[MODE * 32 + b * NHEAD + h],
                      __float_as_uint(fmaxf(vmax, 1e-20f)));
        }
    }
}

// ======================= Flash attention (s8; single-word QKV, dual P) =======
// B-fragment pairing for brow/bchk mapping: {f0,f1} rows0-7, {f2,f3} rows8-15.
__global__ __launch_bounds__(128, 4)
void attn_s8()
{
    extern __shared__ char smraw[];
    const uint32_t sb = smem_u32(smraw);
    const int tid = threadIdx.x, lane = tid & 31, w = tid >> 5;
    const int bh = blockIdx.y;
    const int q0 = blockIdx.x * 64;

    const signed char* Qh = (const signed char*)(g_pool + OFF_QQH) + (size_t)bh * SEQ * HDIM;
    const signed char* Kh = (const signed char*)(g_pool + OFF_KQH) + (size_t)bh * SEQ * HDIM;
    const signed char* Th = (const signed char*)(g_pool + OFF_VTH) + (size_t)bh * HDIM * SEQ;

    const float cS = g_qkvmax[bh] * g_qkvmax[32 + bh] * (1.f / (16129.f * 8.f));
    const float cV = g_qkvmax[64 + bh] * (1.f / 16129.f);

    {
        int row = tid >> 1;
        #pragma unroll
        for (int i = 0; i < 2; i++) {
            int c = (tid & 1) * 2 + i;
            cpasync16(sb + row * 80 + c * 16, Qh + (size_t)(q0 + row) * HDIM + c * 16);
        }
    }

    auto kv_issue = [&](int j, int st) {
        uint32_t base = sb + 5120 + st * 10240;
        int row = tid >> 1;
        #pragma unroll
        for (int i = 0; i < 2; i++) {
            int c = (tid & 1) * 2 + i;
            cpasync16(base + row * 80 + c * 16,
                      Kh + (size_t)(j * 64 + row) * HDIM + c * 16);
            cpasync16(base + 5120 + row * 80 + c * 16,
                      Th + (size_t)row * SEQ + j * 64 + c * 16);
        }
        asm volatile("cp.async.commit_group;" ::: "memory");
    };

    kv_issue(0, 0);

    const int arow = ((lane >> 3) & 1) * 8 + (lane & 7);
    const int achk = lane >> 4;
    const int brow = ((lane >> 4) & 1) * 8 + (lane & 7);
    const int bchk = (lane >> 3) & 1;
    const uint32_t qA0 = sb + (uint32_t)(w * 16 + arow) * 80 + achk * 16;
    const uint32_t Pw  = sb + 25600 + (uint32_t)w * 2560;
    const uint32_t pA0 = Pw + (uint32_t)arow * 80 + achk * 16;
    const int r = lane >> 2, cbase = (lane & 3) * 2;

    float acc[8][4];
    #pragma unroll
    for (int j = 0; j < 8; j++)
        #pragma unroll
        for (int q = 0; q < 4; q++) acc[j][q] = 0.f;
    float m0 = -1e30f, m1 = -1e30f, l0 = 0.f, l1 = 0.f;

    for (int jt = 0; jt < SEQ / 64; jt++) {
        if (jt + 1 < SEQ / 64) {
            kv_issue(jt + 1, (jt + 1) & 1);
            asm volatile("cp.async.wait_group 1;" ::: "memory");
        } else {
            asm volatile("cp.async.wait_group 0;" ::: "memory");
        }
        __syncthreads();
        const uint32_t stg = sb + 5120 + (jt & 1) * 10240;

        uint32_t qf[2][4];
        #pragma unroll
        for (int t = 0; t < 2; t++) ldsm4(qf[t], qA0 + t * 32);

        float s[8][4];
        #pragma unroll
        for (int np = 0; np < 4; np++) {
            int a1[2][4] = {{0,0,0,0},{0,0,0,0}};
            #pragma unroll
            for (int t = 0; t < 2; t++) {
                uint32_t kf[4];
                uint32_t ka = stg + (uint32_t)(np * 16 + brow) * 80 + bchk * 16 + t * 32;
                ldsm4(kf, ka);
                uint32_t b0[2] = { kf[0], kf[1] }, b1[2] = { kf[2], kf[3] };
                mma_s8(a1[0], qf[t], b0);
                mma_s8(a1[1], qf[t], b1);
            }
            #pragma unroll
            for (int o = 0; o < 2; o++)
                #pragma unroll
                for (int q = 0; q < 4; q++)
                    s[2 * np + o][q] = cS * (float)a1[o][q];
        }

        float mx0 = -1e30f, mx1 = -1e30f;
        #pragma unroll
        for (int j = 0; j < 8; j++) {
            mx0 = fmaxf(mx0, fmaxf(s[j][0], s[j][1]));
            mx1 = fmaxf(mx1, fmaxf(s[j][2], s[j][3]));
        }
        mx0 = fmaxf(mx0, __shfl_xor_sync(0xffffffffu, mx0, 1));
        mx0 = fmaxf(mx0, __shfl_xor_sync(0xffffffffu, mx0, 2));
        mx1 = fmaxf(mx1, __shfl_xor_sync(0xffffffffu, mx1, 1));
        mx1 = fmaxf(mx1, __shfl_xor_sync(0xffffffffu, mx1, 2));
        float mn0 = fmaxf(m0, mx0), mn1 = fmaxf(m1, mx1);
        float cr0 = __expf(m0 - mn0), cr1 = __expf(m1 - mn1);
        float sum0 = 0.f, sum1 = 0.f;
        #pragma unroll
        for (int j = 0; j < 8; j++) {
            s[j][0] = __expf(s[j][0] - mn0); sum0 += s[j][0];
            s[j][1] = __expf(s[j][1] - mn0); sum0 += s[j][1];
            s[j][2] = __expf(s[j][2] - mn1); sum1 += s[j][2];
            s[j][3] = __expf(s[j][3] - mn1); sum1 += s[j][3];
        }
        sum0 += __shfl_xor_sync(0xffffffffu, sum0, 1);
        sum0 += __shfl_xor_sync(0xffffffffu, sum0, 2);
        sum1 += __shfl_xor_sync(0xffffffffu, sum1, 1);
        sum1 += __shfl_xor_sync(0xffffffffu, sum1, 2);
        l0 = l0 * cr0 + sum0;  m0 = mn0;
        l1 = l1 * cr1 + sum1;  m1 = mn1;
        #pragma unroll
        for (int j = 0; j < 8; j++) {
            acc[j][0] *= cr0; acc[j][1] *= cr0;
            acc[j][2] *= cr1; acc[j][3] *= cr1;
        }

        #pragma unroll
        for (int j = 0; j < 8; j++) {
            int h0i = __float2int_rn(s[j][0] * 127.f);
            int l0i = min(127, max(-127, __float2int_rn((s[j][0] * 127.f - h0i) * 256.f)));
            int h1i = __float2int_rn(s[j][1] * 127.f);
            int l1i = min(127, max(-127, __float2int_rn((s[j][1] * 127.f - h1i) * 256.f)));
            int h2i = __float2int_rn(s[j][2] * 127.f);
            int l2i = min(127, max(-127, __float2int_rn((s[j][2] * 127.f - h2i) * 256.f)));
            int h3i = __float2int_rn(s[j][3] * 127.f);
            int l3i = min(127, max(-127, __float2int_rn((s[j][3] * 127.f - h3i) * 256.f)));
            uint32_t col = 8 * j + cbase;
            sts_u16(Pw + r * 80 + col,          (h0i & 0xFF) | ((h1i & 0xFF) << 8));
            sts_u16(Pw + 1280 + r * 80 + col,   (l0i & 0xFF) | ((l1i & 0xFF) << 8));
            sts_u16(Pw + (r + 8) * 80 + col,        (h2i & 0xFF) | ((h3i & 0xFF) << 8));
            sts_u16(Pw + 1280 + (r + 8) * 80 + col, (l2i & 0xFF) | ((l3i & 0xFF) << 8));
        }
        __syncwarp();

        uint32_t pfh[2][4], pfl[2][4];
        #pragma unroll
        for (int t = 0; t < 2; t++) {
            ldsm4(pfh[t], pA0 + t * 32);
            ldsm4(pfl[t], pA0 + 1280 + t * 32);
        }

        #pragma unroll
        for (int np = 0; np < 4; np++) {
            int a1[2][4] = {{0,0,0,0},{0,0,0,0}};
            int a2[2][4] = {{0,0,0,0},{0,0,0,0}};
            #pragma unroll
            for (int t = 0; t < 2; t++) {
                uint32_t vf[4];
                uint32_t va = stg + 5120 + (uint32_t)(np * 16 + brow) * 80 + bchk * 16 + t * 32;
                ldsm4(vf, va);
                uint32_t b0[2] = { vf[0], vf[1] }, b1[2] = { vf[2], vf[3] };
                mma_s8(a1[0], pfh[t], b0); mma_s8(a2[0], pfl[t], b0);
                mma_s8(a1[1], pfh[t], b1); mma_s8(a2[1], pfl[t], b1);
            }
            #pragma unroll
            for (int o = 0; o < 2; o++)
                #pragma unroll
                for (int q = 0; q < 4; q++)
                    acc[2 * np + o][q] += (float)a1[o][q] + (float)a2[o][q] * (1.f / 256.f);
        }
        __syncthreads();
    }

    const int b = bh >> 4, h = bh & 15;
    const float inv0 = cV / l0, inv1 = cV / l1;
    const int row0 = q0 + w * 16 + r;
    float* OB = (float*)(g_pool + OFF_O) + ((size_t)b * SEQ) * DMODEL + (size_t)h * HDIM;
    #pragma unroll
    for (int j = 0; j < 8; j++) {
        int col = 8 * j + cbase;
        *(float2*)(OB + (size_t)row0 * DMODEL + col) =
            make_float2(acc[j][0] * inv0, acc[j][1] * inv0);
        *(float2*)(OB + (size_t)(row0 + 8) * DMODEL + col) =
            make_float2(acc[j][2] * inv1, acc[j][3] * inv1);
    }
}

// =============================== LayerNorm ===================================
__global__ __launch_bounds__(256)
void ln_kernel(const float* __restrict__ g, const float* __restrict__ b,
               float* __restrict__ dstArg, int which)
{
    __shared__ float red[8];
    __shared__ float bc;
    const int tid = threadIdx.x;
    const int row = blockIdx.x;
    const float* src = (which == 0) ? (const float*)(g_pool + OFF_T1)
                                    : (const float*)(g_pool + OFF_Z);
    float* dst = (which == 0) ? (float*)(g_pool + OFF_Y) : dstArg;

    float4 v = ((const float4*)(src + (size_t)row * DMODEL))[tid];
    float s = v.x + v.y + v.z + v.w;
    #pragma unroll
    for (int o = 16; o >= 1; o >>= 1) s += __shfl_xor_sync(0xffffffffu, s, o);
    if ((tid & 31) == 0) red[tid >> 5] = s;
    __syncthreads();
    if (tid == 0) {
        float t = 0.f;
        #pragma unroll
        for (int i = 0; i < 8; i++) t += red[i];
        bc = t;
    }
    __syncthreads();
    float mu = bc * (1.f / DMODEL);
    float dx = v.x - mu, dy = v.y - mu, dz = v.z - mu, dw = v.w - mu;
    float s2 = dx * dx + dy * dy + dz * dz + dw * dw;
    #pragma unroll
    for (int o = 16; o >= 1; o >>= 1) s2 += __shfl_xor_sync(0xffffffffu, s2, o);
    __syncthreads();
    if ((tid & 31) == 0) red[tid >> 5] = s2;
    __syncthreads();
    if (tid == 0) {
        float t = 0.f;
        #pragma unroll
        for (int i = 0; i < 8; i++) t += red[i];
        bc = t;
    }
    __syncthreads();
    float rstd = rsqrtf(bc * (1.f / DMODEL) + 1e-5f);
    float4 gg = ((const float4*)g)[tid];
    float4 bb = ((const float4*)b)[tid];
    float4 o4;
    o4.x = dx * rstd * gg.x + bb.x;
    o4.y = dy * rstd * gg.y + bb.y;
    o4.z = dz * rstd * gg.z + bb.z;
    o4.w = dw * rstd * gg.w + bb.w;
    ((float4*)(dst + (size_t)row * DMODEL))[tid] = o4;

    if (which == 0) {
        float am = fmaxf(fmaxf(fabsf(o4.x), fabsf(o4.y)), fmaxf(fabsf(o4.z), fabsf(o4.w)));
        #pragma unroll
        for (int o = 16; o >= 1; o >>= 1) am = fmaxf(am, __shfl_xor_sync(0xffffffffu, am, o));
        __syncthreads();
        if ((tid & 31) == 0) red[tid >> 5] = am;
        __syncthreads();
        if (tid == 0) {
            float t = 1e-20f;
            #pragma unroll
            for (int i = 0; i < 8; i++) t = fmaxf(t, red[i]);
            bc = t; g_sy[row] = t;
        }
        __syncthreads();
        float inv = 127.f / bc;
        char4 h4, l4;
        q_split(o4.x * inv, h4.x, l4.x);
        q_split(o4.y * inv, h4.y, l4.y);
        q_split(o4.z * inv, h4.z, l4.z);
        q_split(o4.w * inv, h4.w, l4.w);
        size_t idx = (size_t)row * DMODEL + tid * 4;
        *(char4*)((signed char*)(g_pool + OFF_YQH) + idx) = h4;
        *(char4*)((signed char*)(g_pool + OFF_YQL) + idx) = l4;
    }
}

// ================================ launch =====================================
extern "C" void kernel_launch(void* const* d_in, const int* in_sizes, int n_in,
                              void* d_out, int out_size)
{
    (void)in_sizes; (void)n_in; (void)out_size;
    const float* X   = (const float*)d_in[0];
    const float* Wq  = (const float*)d_in[1];
    const float* bq  = (const float*)d_in[2];
    const float* Wk  = (const float*)d_in[3];
    const float* bk  = (const float*)d_in[4];
    const float* Wv  = (const float*)d_in[5];
    const float* bv  = (const float*)d_in[6];
    const float* Wo  = (const float*)d_in[7];
    const float* bo  = (const float*)d_in[8];
    const float* l1g = (const float*)d_in[9];
    const float* l1b = (const float*)d_in[10];
    const float* W1  = (const float*)d_in[11];
    const float* b1  = (const float*)d_in[12];
    const float* W2  = (const float*)d_in[13];
    const float* b2  = (const float*)d_in[14];
    const float* l2g = (const float*)d_in[15];
    const float* l2b = (const float*)d_in[16];

    const int g8_smem = 2 * 30720;
    cudaFuncSetAttribute(gemm_i8<0>, cudaFuncAttributeMaxDynamicSharedMemorySize, g8_smem);
    cudaFuncSetAttribute(gemm_i8<1>, cudaFuncAttributeMaxDynamicSharedMemorySize, g8_smem);
    cudaFuncSetAttribute(gemm_i8<2>, cudaFuncAttributeMaxDynamicSharedMemorySize, g8_smem);
    cudaFuncSetAttribute(gemm_i8<3>, cudaFuncAttributeMaxDynamicSharedMemorySize, g8_smem);
    cudaFuncSetAttribute(gemm_i8<4>, cudaFuncAttributeMaxDynamicSharedMemorySize, g8_smem);
    cudaFuncSetAttribute(gemm_i8<5>, cudaFuncAttributeMaxDynamicSharedMemorySize, g8_smem);
    const int attn_smem = 35840;
    cudaFuncSetAttribute(attn_s8, cudaFuncAttributeMaxDynamicSharedMemorySize, attn_smem);

    dim3 thr(256);

    zero_scales<<<37, thr>>>();
    quant_rows<1024, 0><<<MB, thr>>>(X);
    wcolmax<<<dim3(4, 32),  thr>>>(Wq, 1024, 1024, 1, 0);
    wcolmax<<<dim3(4, 32),  thr>>>(Wk, 1024, 1024, 1, 1024);
    wcolmax<<<dim3(4, 32),  thr>>>(Wv, 1024, 1024, 1, 2048);
    wcolmax<<<dim3(4, 32),  thr>>>(Wo, 1024, 1024, 0, 3072);
    wcolmax<<<dim3(4, 32),  thr>>>(W2, 4096, 1024, 0, 4096);
    wcolmax<<<dim3(16, 32), thr>>>(W1, 1024, 4096, 0, 5120);
    conv_wq<<<dim3(32, 32),  thr>>>(Wq, 1024, 1024, 0, 0);
    conv_wq<<<dim3(32, 32),  thr>>>(Wk, 1024, 1024, 1, 1024);
    conv_wq<<<dim3(32, 32),  thr>>>(Wv, 1024, 1024, 2, 2048);
    conv_wq<<<dim3(32, 32),  thr>>>(Wo, 1024, 1024, 3, 3072);
    conv_wq<<<dim3(128, 32), thr>>>(W1, 1024, 4096, 4, 5120);
    conv_wq<<<dim3(32, 128), thr>>>(W2, 4096, 1024, 5, 4096);

    // QKV projections (1-limb) with fused per-bh absmax
    gemm_i8<0><<<dim3(16, 32), thr, g8_smem>>>(bq, nullptr);
    gemm_i8<1><<<dim3(16, 32), thr, g8_smem>>>(bk, nullptr);
    gemm_i8<2><<<dim3(16, 32), thr, g8_smem>>>(bv, nullptr);

    quant_qk2<<<8192, thr>>>();
    quant_vt<<<dim3(64, 2, 32), thr>>>();

    attn_s8<<<dim3(32, 32), dim3(128), attn_smem>>>();

    quant_rows<1024, 1><<<MB, thr>>>(nullptr);
    gemm_i8<3><<<dim3(16, 32), thr, g8_smem>>>(bo, X);
    ln_kernel<<<MB, thr>>>(l1g, l1b, nullptr, 0);

    gemm_i8<4><<<dim3(64, 32), thr, g8_smem>>>(b1, nullptr);
    quant_rows<4096, 2><<<MB, thr>>>(nullptr);
    gemm_i8<5><<<dim3(16, 32), thr, g8_smem>>>(b2, nullptr);
    ln_kernel<<<MB, thr>>>(l2g, l2b, (float*)d_out, 1);
}

// round 17
// speedup vs baseline: 1.2345x; 1.0447x over previous
#include <cuda_runtime.h>
#include <cuda_bf16.h>
#include <cstdint>

#define MB      4096
#define DMODEL  1024
#define NHEAD   16
#define HDIM    64
#define SEQ     2048
#define FF      4096

// ------------------------- pooled scratch (lifetime-overlaid) ----------------
constexpr size_t MiB = 1024u * 1024u;
__device__ __align__(1024) unsigned char g_pool[136 * MiB];

constexpr size_t OFF_QF  = 0 * MiB;     // fp32 16MB   (phase 2-2.5)
constexpr size_t OFF_KF  = 16 * MiB;
constexpr size_t OFF_VF  = 32 * MiB;
constexpr size_t OFF_O   = 48 * MiB;    // fp32 16MB   (phase 3-4)
constexpr size_t OFF_FF  = 0 * MiB;     // fp32 64MB   (phase 7-8)
constexpr size_t OFF_QQH = 64 * MiB;    // s8 4MB (single-word)
constexpr size_t OFF_KQH = 68 * MiB;
constexpr size_t OFF_VTH = 72 * MiB;    // s8 [bh][HD][S]
constexpr size_t OFF_XQH = 88 * MiB;    // s8 4MB (single-word; phase 1-2)
constexpr size_t OFF_FQH = 64 * MiB;    // s8 16MB each (phase 8-9)
constexpr size_t OFF_FQL = 80 * MiB;
constexpr size_t OFF_T1  = 96 * MiB;    // fp32 16MB   (phase 5-6)
constexpr size_t OFF_Z   = 96 * MiB;    // fp32 16MB   (phase 9-10)
constexpr size_t OFF_Y   = 112 * MiB;   // fp32 16MB   (phase 6-9)
constexpr size_t OFF_OQH = 128 * MiB;   // s8 4MB (single-word; phase 4-5)
constexpr size_t OFF_YQH = 128 * MiB;   // s8 4MB each (phase 6-7; Oq dead)
constexpr size_t OFF_YQL = 132 * MiB;

// quantized transposed weights [N][K] + scales
__device__ __align__(128) signed char g_Wqh_q[DMODEL * DMODEL], g_Wql_q[DMODEL * DMODEL];
__device__ __align__(128) signed char g_Wkh_q[DMODEL * DMODEL], g_Wkl_q[DMODEL * DMODEL];
__device__ __align__(128) signed char g_Wvh_q[DMODEL * DMODEL], g_Wvl_q[DMODEL * DMODEL];
__device__ __align__(128) signed char g_Woh_q[DMODEL * DMODEL], g_Wol_q[DMODEL * DMODEL];
__device__ __align__(128) signed char g_W1h_q[FF * DMODEL],     g_W1l_q[FF * DMODEL];
__device__ __align__(128) signed char g_W2h_q[DMODEL * FF],     g_W2l_q[DMODEL * FF];
__device__ __align__(128) float g_wmax[9216];
__device__ __align__(128) float g_qkvmax[96];   // Q 0..31, K 32..63, V 64..95
__device__ __align__(128) float g_sX [MB];
__device__ __align__(128) float g_sO [MB];
__device__ __align__(128) float g_sy [MB];
__device__ __align__(128) float g_sff[MB];

// ------------------------------ helpers --------------------------------------
__device__ __forceinline__ uint32_t smem_u32(const void* p) {
    uint32_t a;
    asm("{ .reg .u64 t; cvta.to.shared.u64 t, %1; cvt.u32.u64 %0, t; }"
        : "=r"(a) : "l"(p));
    return a;
}
__device__ __forceinline__ void cpasync16(uint32_t s, const void* g) {
    asm volatile("cp.async.cg.shared.global [%0], [%1], 16;"
                 :: "r"(s), "l"(g) : "memory");
}
__device__ __forceinline__ void ldsm4(uint32_t* r, uint32_t addr) {
    asm volatile("ldmatrix.sync.aligned.m8n8.x4.shared.b16 {%0,%1,%2,%3}, [%4];"
        : "=r"(r[0]), "=r"(r[1]), "=r"(r[2]), "=r"(r[3]) : "r"(addr));
}
__device__ __forceinline__ void sts_u16(uint32_t addr, uint32_t v) {
    asm volatile("st.shared.u16 [%0], %1;" :: "r"(addr), "r"(v) : "memory");
}
__device__ __forceinline__ void mma_s8(int* c, const uint32_t* a, const uint32_t* b) {
    asm volatile("mma.sync.aligned.m16n8k32.row.col.s32.s8.s8.s32 "
        "{%0,%1,%2,%3}, {%4,%5,%6,%7}, {%8,%9}, {%0,%1,%2,%3};"
        : "+r"(c[0]), "+r"(c[1]), "+r"(c[2]), "+r"(c[3])
        : "r"(a[0]), "r"(a[1]), "r"(a[2]), "r"(a[3]), "r"(b[0]), "r"(b[1]));
}
__device__ __forceinline__ void q_split(float q, signed char& hi, signed char& lo) {
    int h = __float2int_rn(q);
    int l = __float2int_rn((q - (float)h) * 256.f);
    l = max(-127, min(127, l));
    hi = (signed char)h;
    lo = (signed char)l;
}

// ------------------------- quantization kernels ------------------------------
// SEL 0: X(arg)->Xq single/sX ; SEL 1: O->Oq single/sO ; SEL 2: ff->fq dual/sff
template<int C, int SEL>
__global__ __launch_bounds__(256)
void quant_rows(const float* __restrict__ srcArg)
{
    const float* src;
    signed char *qh, *ql;
    float* smax;
    if constexpr (SEL == 0) {
        src = srcArg;
        qh = (signed char*)(g_pool + OFF_XQH); ql = nullptr;
        smax = g_sX;
    } else if constexpr (SEL == 1) {
        src = (const float*)(g_pool + OFF_O);
        qh = (signed char*)(g_pool + OFF_OQH); ql = nullptr;
        smax = g_sO;
    } else {
        src = (const float*)(g_pool + OFF_FF);
        qh = (signed char*)(g_pool + OFF_FQH); ql = (signed char*)(g_pool + OFF_FQL);
        smax = g_sff;
    }

    __shared__ float red[8];
    __shared__ float bc;
    const int tid = threadIdx.x, row = blockIdx.x;
    constexpr int V = C / 1024;
    const float4* s4 = (const float4*)(src + (size_t)row * C);
    float4 v[V];
    float mx = 0.f;
    #pragma unroll
    for (int i = 0; i < V; i++) {
        v[i] = s4[tid + i * 256];
        mx = fmaxf(mx, fmaxf(fmaxf(fabsf(v[i].x), fabsf(v[i].y)),
                             fmaxf(fabsf(v[i].z), fabsf(v[i].w))));
    }
    #pragma unroll
    for (int o = 16; o >= 1; o >>= 1) mx = fmaxf(mx, __shfl_xor_sync(0xffffffffu, mx, o));
    if ((tid & 31) == 0) red[tid >> 5] = mx;
    __syncthreads();
    if (tid == 0) {
        float t = 1e-20f;
        #pragma unroll
        for (int i = 0; i < 8; i++) t = fmaxf(t, red[i]);
        bc = t; smax[row] = t;
    }
    __syncthreads();
    const float inv = 127.f / bc;
    #pragma unroll
    for (int i = 0; i < V; i++) {
        size_t idx = (size_t)row * C + (tid + i * 256) * 4;
        if constexpr (SEL == 2) {
            char4 h4, l4;
            q_split(v[i].x * inv, h4.x, l4.x);
            q_split(v[i].y * inv, h4.y, l4.y);
            q_split(v[i].z * inv, h4.z, l4.z);
            q_split(v[i].w * inv, h4.w, l4.w);
            *(char4*)(qh + idx) = h4;
            *(char4*)(ql + idx) = l4;
        } else {
            char4 h4;
            h4.x = (signed char)__float2int_rn(v[i].x * inv);
            h4.y = (signed char)__float2int_rn(v[i].y * inv);
            h4.z = (signed char)__float2int_rn(v[i].z * inv);
            h4.w = (signed char)__float2int_rn(v[i].w * inv);
            *(char4*)(qh + idx) = h4;
        }
    }
}

__global__ __launch_bounds__(256)
void zero_scales() {
    int i = blockIdx.x * 256 + threadIdx.x;
    if (i < 9216) g_wmax[i] = 0.f;
    if (i < 96)   g_qkvmax[i] = 0.f;
}

__global__ __launch_bounds__(256)
void wcolmax(const float* __restrict__ w, int K, int N, int qkv, int moff)
{
    int n = blockIdx.x * 256 + threadIdx.x;
    int kspan = K / 32;
    int k0 = blockIdx.y * kspan;
    float m = 0.f;
    for (int k = k0; k < k0 + kspan; k++) {
        size_t idx = qkv ? ((size_t)(n >> 6) * K * 64 + (size_t)k * 64 + (n & 63))
                         : ((size_t)k * N + n);
        m = fmaxf(m, fabsf(w[idx]));
    }
    atomicMax((unsigned int*)&g_wmax[moff + n], __float_as_uint(m));
}

__global__ __launch_bounds__(256)
void conv_wq(const float* __restrict__ in, int K, int N, int sel, int moff)
{
    signed char *oh, *ol;
    switch (sel) {
        case 0: oh = g_Wqh_q; ol = g_Wql_q; break;
        case 1: oh = g_Wkh_q; ol = g_Wkl_q; break;
        case 2: oh = g_Wvh_q; ol = g_Wvl_q; break;
        case 3: oh = g_Woh_q; ol = g_Wol_q; break;
        case 4: oh = g_W1h_q; ol = g_W1l_q; break;
        default: oh = g_W2h_q; ol = g_W2l_q; break;
    }
    const bool qkv = sel < 3;
    __shared__ float tile[32][33];
    int tx = threadIdx.x & 31, ty = threadIdx.x >> 5;
    int n0 = blockIdx.x * 32, k0 = blockIdx.y * 32;
    #pragma unroll
    for (int j = 0; j < 4; j++) {
        int k = k0 + ty + j * 8, n = n0 + tx;
        size_t idx = qkv ? ((size_t)(n >> 6) * K * 64 + (size_t)k * 64 + (n & 63))
                         : ((size_t)k * N + n);
        tile[ty + j * 8][tx] = in[idx];
    }
    __syncthreads();
    #pragma unroll
    for (int j = 0; j < 4; j++) {
        int n = n0 + ty + j * 8, k = k0 + tx;
        float inv = 127.f / fmaxf(g_wmax[moff + n], 1e-20f);
        signed char hi, lo;
        q_split(tile[tx][ty + j * 8] * inv, hi, lo);
        oh[(size_t)n * K + k] = hi;
        ol[(size_t)n * K + k] = lo;
    }
}

// Q and K single-word quant in one launch (blocks [0,4096) = Q, [4096,8192) = K)
__global__ __launch_bounds__(256)
void quant_qk2()
{
    const int sel = (blockIdx.x >= 4096) ? 1 : 0;
    const int blk = blockIdx.x & 4095;
    const float* src = (const float*)(g_pool + (sel == 0 ? OFF_QF : OFF_KF));
    signed char* qh  = (signed char*)(g_pool + (sel == 0 ? OFF_QQH : OFF_KQH));
    int fi = (blk * 256 + threadIdx.x) * 4;
    int bh = fi >> 17;
    float inv = 127.f / g_qkvmax[(sel == 0 ? 0 : 32) + bh];
    float4 v = *(const float4*)(src + fi);
    char4 h4;
    h4.x = (signed char)__float2int_rn(v.x * inv);
    h4.y = (signed char)__float2int_rn(v.y * inv);
    h4.z = (signed char)__float2int_rn(v.z * inv);
    h4.w = (signed char)__float2int_rn(v.w * inv);
    *(char4*)(qh + fi) = h4;
}

// V fp32 [bh][s][hd] -> transposed single-word s8 [bh][hd][s]
__global__ __launch_bounds__(256)
void quant_vt()
{
    __shared__ float tile[32][33];
    const int bh = blockIdx.z;
    const int s0 = blockIdx.x * 32, h0 = blockIdx.y * 32;
    const int tx = threadIdx.x & 31, ty = threadIdx.x >> 5;
    const float* VF = (const float*)(g_pool + OFF_VF) + (size_t)bh * SEQ * HDIM;
    signed char* TH = (signed char*)(g_pool + OFF_VTH) + (size_t)bh * HDIM * SEQ;
    #pragma unroll
    for (int j = 0; j < 4; j++)
        tile[ty + j * 8][tx] = VF[(size_t)(s0 + ty + j * 8) * HDIM + h0 + tx];
    __syncthreads();
    float inv = 127.f / g_qkvmax[64 + bh];
    #pragma unroll
    for (int j = 0; j < 4; j++) {
        int r = ty + j * 8;
        TH[(size_t)(h0 + r) * SEQ + s0 + tx] =
            (signed char)__float2int_rn(tile[tx][r] * inv);
    }
}

// ------------------------------ int8 GEMM ------------------------------------
// LIMBS: 1 (A single x B single), 2 (A single x B dual), 3 (A dual x B dual)
template<int MODE>
__global__ __launch_bounds__(256)
void gemm_i8(const float* __restrict__ bias, const float* __restrict__ resid)
{
    constexpr int KD    = (MODE == 5) ? FF : DMODEL;
    constexpr int NC    = KD / 64;
    constexpr int STG   = 30720;
    constexpr int LIMBS = (MODE <= 2) ? 1 : (MODE == 3) ? 2 : 3;

    extern __shared__ char smraw[];
    const uint32_t sb = smem_u32(smraw);

    const int tid = threadIdx.x, wid = tid >> 5, lane = tid & 31;
    const int wr = wid >> 1, wc = wid & 1;
    const int m0 = blockIdx.y * 128, n0 = blockIdx.x * 64;

    const signed char *Ah, *Al, *Bh, *Bl;
    const float *sAm, *sBm;
    if constexpr (MODE == 0) {
        Ah = (const signed char*)(g_pool + OFF_XQH); Al = nullptr;
        Bh = g_Wqh_q; Bl = nullptr; sAm = g_sX; sBm = g_wmax + 0;
    } else if constexpr (MODE == 1) {
        Ah = (const signed char*)(g_pool + OFF_XQH); Al = nullptr;
        Bh = g_Wkh_q; Bl = nullptr; sAm = g_sX; sBm = g_wmax + 1024;
    } else if constexpr (MODE == 2) {
        Ah = (const signed char*)(g_pool + OFF_XQH); Al = nullptr;
        Bh = g_Wvh_q; Bl = nullptr; sAm = g_sX; sBm = g_wmax + 2048;
    } else if constexpr (MODE == 3) {
        Ah = (const signed char*)(g_pool + OFF_OQH); Al = nullptr;
        Bh = g_Woh_q; Bl = g_Wol_q; sAm = g_sO; sBm = g_wmax + 3072;
    } else if constexpr (MODE == 4) {
        Ah = (const signed char*)(g_pool + OFF_YQH); Al = (const signed char*)(g_pool + OFF_YQL);
        Bh = g_W1h_q; Bl = g_W1l_q; sAm = g_sy; sBm = g_wmax + 5120;
    } else {
        Ah = (const signed char*)(g_pool + OFF_FQH); Al = (const signed char*)(g_pool + OFF_FQL);
        Bh = g_W2h_q; Bl = g_W2l_q; sAm = g_sff; sBm = g_wmax + 4096;
    }

    const signed char* rAh = Ah + (size_t)m0 * KD;
    const signed char* rAl = (LIMBS == 3) ? Al + (size_t)m0 * KD : nullptr;
    const signed char* rBh = Bh + (size_t)n0 * KD;
    const signed char* rBl = (LIMBS >= 2) ? Bl + (size_t)n0 * KD : nullptr;

    const int aldRow = tid >> 1, aldC0 = (tid & 1) * 2;
    const int bldRow = tid >> 2, bldC  = tid & 3;

    auto issue = [&](int k0, int st) {
        uint32_t base = sb + st * STG;
        #pragma unroll
        for (int i = 0; i < 2; i++) {
            int c = aldC0 + i;
            cpasync16(base + aldRow * 80 + c * 16,
                      rAh + (size_t)aldRow * KD + k0 + c * 16);
            if constexpr (LIMBS == 3)
                cpasync16(base + 10240 + aldRow * 80 + c * 16,
                          rAl + (size_t)aldRow * KD + k0 + c * 16);
        }
        cpasync16(base + 20480 + bldRow * 80 + bldC * 16,
                  rBh + (size_t)bldRow * KD + k0 + bldC * 16);
        if constexpr (LIMBS >= 2)
            cpasync16(base + 25600 + bldRow * 80 + bldC * 16,
                      rBl + (size_t)bldRow * KD + k0 + bldC * 16);
        asm volatile("cp.async.commit_group;" ::: "memory");
    };

    int acc1[2][4][4], acc2[2][4][4];
    #pragma unroll
    for (int i = 0; i < 2; i++)
        #pragma unroll
        for (int j = 0; j < 4; j++)
            #pragma unroll
            for (int q = 0; q < 4; q++) { acc1[i][j][q] = 0; acc2[i][j][q] = 0; }

    const int arow = ((lane >> 3) & 1) * 8 + (lane & 7);
    const int achk = lane >> 4;
    const uint32_t aA0 = sb + (uint32_t)(wr * 32 + arow) * 80 + achk * 16;
    const uint32_t bA0 = sb + 20480 + (uint32_t)(wc * 32 + arow) * 80 + achk * 16;

    issue(0, 0);

    for (int ct = 0; ct < NC; ct++) {
        if (ct + 1 < NC) {
            issue((ct + 1) * 64, (ct + 1) & 1);
            asm volatile("cp.async.wait_group 1;" ::: "memory");
        } else {
            asm volatile("cp.async.wait_group 0;" ::: "memory");
        }
        __syncthreads();
        const uint32_t off = (ct & 1) ? (uint32_t)STG : 0u;
        #pragma unroll
        for (int s = 0; s < 2; s++) {
            uint32_t bh[2][4], bl[2][4];
            #pragma unroll
            for (int bj = 0; bj < 2; bj++) {
                uint32_t ba = bA0 + off + bj * (16 * 80) + s * 32;
                ldsm4(bh[bj], ba);
                if constexpr (LIMBS >= 2) ldsm4(bl[bj], ba + 5120);
            }
            #pragma unroll
            for (int mi = 0; mi < 2; mi++) {
                uint32_t ah[4], al[4];
                uint32_t aa = aA0 + off + mi * (16 * 80) + s * 32;
                ldsm4(ah, aa);
                if constexpr (LIMBS == 3) ldsm4(al, aa + 10240);
                #pragma unroll
                for (int nj = 0; nj < 4; nj++) {
                    int bj = nj >> 1, oc = nj & 1;
                    uint32_t bfh[2] = { bh[bj][oc], bh[bj][oc + 2] };
                    mma_s8(acc1[mi][nj], ah, bfh);
                    if constexpr (LIMBS >= 2) {
                        uint32_t bfl[2] = { bl[bj][oc], bl[bj][oc + 2] };
                        mma_s8(acc2[mi][nj], ah, bfl);
                        if constexpr (LIMBS == 3) mma_s8(acc2[mi][nj], al, bfh);
                    }
                }
            }
        }
        __syncthreads();
    }

    const int qrow = lane >> 2, qcol = (lane & 3) * 2;
    const int mrow0 = m0 + wr * 32, ncol0 = n0 + wc * 32;

    float2 bias2[4], sB2[4];
    #pragma unroll
    for (int nj = 0; nj < 4; nj++) {
        int n = ncol0 + nj * 8 + qcol;
        bias2[nj] = *(const float2*)(bias + n);
        sB2[nj]   = *(const float2*)(sBm + n);
    }

    float vmax = 0.f;
    #pragma unroll
    for (int mi = 0; mi < 2; mi++) {
        #pragma unroll
        for (int half = 0; half < 2; half++) {
            int m = mrow0 + mi * 16 + qrow + half * 8;
            float sA = sAm[m] * (1.f / 16129.f);
            #pragma unroll
            for (int nj = 0; nj < 4; nj++) {
                int n = ncol0 + nj * 8 + qcol;
                float r0 = (float)acc1[mi][nj][half * 2 + 0];
                float r1 = (float)acc1[mi][nj][half * 2 + 1];
                if constexpr (LIMBS >= 2) {
                    r0 += (float)acc2[mi][nj][half * 2 + 0] * (1.f / 256.f);
                    r1 += (float)acc2[mi][nj][half * 2 + 1] * (1.f / 256.f);
                }
                float v0 = r0 * sA * sB2[nj].x + bias2[nj].x;
                float v1 = r1 * sA * sB2[nj].y + bias2[nj].y;
                if constexpr (MODE <= 2) {
                    float* outf = (float*)(g_pool +
                        (MODE == 0 ? OFF_QF : MODE == 1 ? OFF_KF : OFF_VF));
                    int b = m >> 11, si = m & 2047, h = n >> 6, e = n & 63;
                    size_t idx = (((size_t)(b * NHEAD + h) * SEQ) + si) * HDIM + e;
                    *(float2*)(outf + idx) = make_float2(v0, v1);
                    vmax = fmaxf(vmax, fmaxf(fabsf(v0), fabsf(v1)));
                } else if constexpr (MODE == 3) {
                    size_t idx = (size_t)m * DMODEL + n;
                    float2 rv = *(const float2*)(resid + idx);
                    *(float2*)((float*)(g_pool + OFF_T1) + idx) = make_float2(v0 + rv.x, v1 + rv.y);
                } else if constexpr (MODE == 4) {
                    size_t idx = (size_t)m * FF + n;
                    *(float2*)((float*)(g_pool + OFF_FF) + idx) =
                        make_float2(fmaxf(v0, 0.f), fmaxf(v1, 0.f));
                } else {
                    size_t idx = (size_t)m * DMODEL + n;
                    float2 rv = *(const float2*)((const float*)(g_pool + OFF_Y) + idx);
                    *(float2*)((float*)(g_pool + OFF_Z) + idx) = make_float2(v0 + rv.x, v1 + rv.y);
                }
            }
        }
    }
    if constexpr (MODE <= 2) {   // fused per-bh absmax (b, h constant per warp tile)
        #pragma unroll
        for (int o = 16; o >= 1; o >>= 1)
            vmax = fmaxf(vmax, __shfl_xor_sync(0xffffffffu, vmax, o));
        if (lane == 0) {
            int b = mrow0 >> 11, h = ncol0 >> 6;
            atomicMax((unsigned int*)&g_qkvmax[MODE * 32 + b * NHEAD + h],
                      __float_as_uint(fmaxf(vmax, 1e-20f)));
        }
    }
}

// ======= Flash attention (s8 single-word QKV; single-word P w/ tile scale) ===
// B-fragment pairing for brow/bchk mapping: {f0,f1} rows0-7, {f2,f3} rows8-15.
// P quantized per-row-per-tile: pmax = exp(mx - mn) bounds p; store p*127/pmax,
// rescale mma row-output by pmax (acc is fp32 per-row).
// smem: Q 0..5120 (64x80 s8); KV stages at 5120 + st*10240: K +0, Vt +5120;
// P at 25600 + w*1280 (hi only, 16x80). Total 30720.
__global__ __launch_bounds__(128, 4)
void attn_s8()
{
    extern __shared__ char smraw[];
    const uint32_t sb = smem_u32(smraw);
    const int tid = threadIdx.x, lane = tid & 31, w = tid >> 5;
    const int bh = blockIdx.y;
    const int q0 = blockIdx.x * 64;

    const signed char* Qh = (const signed char*)(g_pool + OFF_QQH) + (size_t)bh * SEQ * HDIM;
    const signed char* Kh = (const signed char*)(g_pool + OFF_KQH) + (size_t)bh * SEQ * HDIM;
    const signed char* Th = (const signed char*)(g_pool + OFF_VTH) + (size_t)bh * HDIM * SEQ;

    const float cS = g_qkvmax[bh] * g_qkvmax[32 + bh] * (1.f / (16129.f * 8.f));
    const float cV = g_qkvmax[64 + bh] * (1.f / 16129.f);

    {
        int row = tid >> 1;
        #pragma unroll
        for (int i = 0; i < 2; i++) {
            int c = (tid & 1) * 2 + i;
            cpasync16(sb + row * 80 + c * 16, Qh + (size_t)(q0 + row) * HDIM + c * 16);
        }
    }

    auto kv_issue = [&](int j, int st) {
        uint32_t base = sb + 5120 + st * 10240;
        int row = tid >> 1;
        #pragma unroll
        for (int i = 0; i < 2; i++) {
            int c = (tid & 1) * 2 + i;
            cpasync16(base + row * 80 + c * 16,
                      Kh + (size_t)(j * 64 + row) * HDIM + c * 16);
            cpasync16(base + 5120 + row * 80 + c * 16,
                      Th + (size_t)row * SEQ + j * 64 + c * 16);
        }
        asm volatile("cp.async.commit_group;" ::: "memory");
    };

    kv_issue(0, 0);

    const int arow = ((lane >> 3) & 1) * 8 + (lane & 7);
    const int achk = lane >> 4;
    const int brow = ((lane >> 4) & 1) * 8 + (lane & 7);
    const int bchk = (lane >> 3) & 1;
    const uint32_t qA0 = sb + (uint32_t)(w * 16 + arow) * 80 + achk * 16;
    const uint32_t Pw  = sb + 25600 + (uint32_t)w * 1280;
    const uint32_t pA0 = Pw + (uint32_t)arow * 80 + achk * 16;
    const int r = lane >> 2, cbase = (lane & 3) * 2;

    float acc[8][4];
    #pragma unroll
    for (int j = 0; j < 8; j++)
        #pragma unroll
        for (int q = 0; q < 4; q++) acc[j][q] = 0.f;
    float m0 = -1e30f, m1 = -1e30f, l0 = 0.f, l1 = 0.f;

    for (int jt = 0; jt < SEQ / 64; jt++) {
        if (jt + 1 < SEQ / 64) {
            kv_issue(jt + 1, (jt + 1) & 1);
            asm volatile("cp.async.wait_group 1;" ::: "memory");
        } else {
            asm volatile("cp.async.wait_group 0;" ::: "memory");
        }
        __syncthreads();
        const uint32_t stg = sb + 5120 + (jt & 1) * 10240;

        uint32_t qf[2][4];
        #pragma unroll
        for (int t = 0; t < 2; t++) ldsm4(qf[t], qA0 + t * 32);

        float s[8][4];
        #pragma unroll
        for (int np = 0; np < 4; np++) {
            int a1[2][4] = {{0,0,0,0},{0,0,0,0}};
            #pragma unroll
            for (int t = 0; t < 2; t++) {
                uint32_t kf[4];
                uint32_t ka = stg + (uint32_t)(np * 16 + brow) * 80 + bchk * 16 + t * 32;
                ldsm4(kf, ka);
                uint32_t b0[2] = { kf[0], kf[1] }, b1[2] = { kf[2], kf[3] };
                mma_s8(a1[0], qf[t], b0);
                mma_s8(a1[1], qf[t], b1);
            }
            #pragma unroll
            for (int o = 0; o < 2; o++)
                #pragma unroll
                for (int q = 0; q < 4; q++)
                    s[2 * np + o][q] = cS * (float)a1[o][q];
        }

        float mx0 = -1e30f, mx1 = -1e30f;
        #pragma unroll
        for (int j = 0; j < 8; j++) {
            mx0 = fmaxf(mx0, fmaxf(s[j][0], s[j][1]));
            mx1 = fmaxf(mx1, fmaxf(s[j][2], s[j][3]));
        }
        mx0 = fmaxf(mx0, __shfl_xor_sync(0xffffffffu, mx0, 1));
        mx0 = fmaxf(mx0, __shfl_xor_sync(0xffffffffu, mx0, 2));
        mx1 = fmaxf(mx1, __shfl_xor_sync(0xffffffffu, mx1, 1));
        mx1 = fmaxf(mx1, __shfl_xor_sync(0xffffffffu, mx1, 2));
        float mn0 = fmaxf(m0, mx0), mn1 = fmaxf(m1, mx1);
        float cr0 = __expf(m0 - mn0), cr1 = __expf(m1 - mn1);
        float sum0 = 0.f, sum1 = 0.f;
        #pragma unroll
        for (int j = 0; j < 8; j++) {
            s[j][0] = __expf(s[j][0] - mn0); sum0 += s[j][0];
            s[j][1] = __expf(s[j][1] - mn0); sum0 += s[j][1];
            s[j][2] = __expf(s[j][2] - mn1); sum1 += s[j][2];
            s[j][3] = __expf(s[j][3] - mn1); sum1 += s[j][3];
        }
        sum0 += __shfl_xor_sync(0xffffffffu, sum0, 1);
        sum0 += __shfl_xor_sync(0xffffffffu, sum0, 2);
        sum1 += __shfl_xor_sync(0xffffffffu, sum1, 1);
        sum1 += __shfl_xor_sync(0xffffffffu, sum1, 2);
        l0 = l0 * cr0 + sum0;  m0 = mn0;
        l1 = l1 * cr1 + sum1;  m1 = mn1;
        #pragma unroll
        for (int j = 0; j < 8; j++) {
            acc[j][0] *= cr0; acc[j][1] *= cr0;
            acc[j][2] *= cr1; acc[j][3] *= cr1;
        }

        // per-row tile pmax = exp(mx - mn) bounds every p in this tile
        float pm0 = fmaxf(__expf(mx0 - mn0), 1e-20f);
        float pm1 = fmaxf(__expf(mx1 - mn1), 1e-20f);
        float iq0 = 127.f / pm0, iq1 = 127.f / pm1;

        // quantize P single-word (p * 127/pmax <= 127) and stage via smem
        #pragma unroll
        for (int j = 0; j < 8; j++) {
            int h0i = __float2int_rn(s[j][0] * iq0);
            int h1i = __float2int_rn(s[j][1] * iq0);
            int h2i = __float2int_rn(s[j][2] * iq1);
            int h3i = __float2int_rn(s[j][3] * iq1);
            uint32_t col = 8 * j + cbase;
            sts_u16(Pw + r * 80 + col,       (h0i & 0xFF) | ((h1i & 0xFF) << 8));
            sts_u16(Pw + (r + 8) * 80 + col, (h2i & 0xFF) | ((h3i & 0xFF) << 8));
        }
        __syncwarp();

        uint32_t pf[2][4];
        #pragma unroll
        for (int t = 0; t < 2; t++) ldsm4(pf[t], pA0 + t * 32);

        // acc += (P_q V_q) * pmax_row  (single P x single V)
        #pragma unroll
        for (int np = 0; np < 4; np++) {
            int a1[2][4] = {{0,0,0,0},{0,0,0,0}};
            #pragma unroll
            for (int t = 0; t < 2; t++) {
                uint32_t vf[4];
                uint32_t va = stg + 5120 + (uint32_t)(np * 16 + brow) * 80 + bchk * 16 + t * 32;
                ldsm4(vf, va);
                uint32_t b0[2] = { vf[0], vf[1] }, b1[2] = { vf[2], vf[3] };
                mma_s8(a1[0], pf[t], b0);
                mma_s8(a1[1], pf[t], b1);
            }
            #pragma unroll
            for (int o = 0; o < 2; o++) {
                acc[2 * np + o][0] += (float)a1[o][0] * pm0;
                acc[2 * np + o][1] += (float)a1[o][1] * pm0;
                acc[2 * np + o][2] += (float)a1[o][2] * pm1;
                acc[2 * np + o][3] += (float)a1[o][3] * pm1;
            }
        }
        __syncthreads();
    }

    const int b = bh >> 4, h = bh & 15;
    const float inv0 = cV / l0, inv1 = cV / l1;
    const int row0 = q0 + w * 16 + r;
    float* OB = (float*)(g_pool + OFF_O) + ((size_t)b * SEQ) * DMODEL + (size_t)h * HDIM;
    #pragma unroll
    for (int j = 0; j < 8; j++) {
        int col = 8 * j + cbase;
        *(float2*)(OB + (size_t)row0 * DMODEL + col) =
            make_float2(acc[j][0] * inv0, acc[j][1] * inv0);
        *(float2*)(OB + (size_t)(row0 + 8) * DMODEL + col) =
            make_float2(acc[j][2] * inv1, acc[j][3] * inv1);
    }
}

// =============================== LayerNorm ===================================
__global__ __launch_bounds__(256)
void ln_kernel(const float* __restrict__ g, const float* __restrict__ b,
               float* __restrict__ dstArg, int which)
{
    __shared__ float red[8];
    __shared__ float bc;
    const int tid = threadIdx.x;
    const int row = blockIdx.x;
    const float* src = (which == 0) ? (const float*)(g_pool + OFF_T1)
                                    : (const float*)(g_pool + OFF_Z);
    float* dst = (which == 0) ? (float*)(g_pool + OFF_Y) : dstArg;

    float4 v = ((const float4*)(src + (size_t)row * DMODEL))[tid];
    float s = v.x + v.y + v.z + v.w;
    #pragma unroll
    for (int o = 16; o >= 1; o >>= 1) s += __shfl_xor_sync(0xffffffffu, s, o);
    if ((tid & 31) == 0) red[tid >> 5] = s;
    __syncthreads();
    if (tid == 0) {
        float t = 0.f;
        #pragma unroll
        for (int i = 0; i < 8; i++) t += red[i];
        bc = t;
    }
    __syncthreads();
    float mu = bc * (1.f / DMODEL);
    float dx = v.x - mu, dy = v.y - mu, dz = v.z - mu, dw = v.w - mu;
    float s2 = dx * dx + dy * dy + dz * dz + dw * dw;
    #pragma unroll
    for (int o = 16; o >= 1; o >>= 1) s2 += __shfl_xor_sync(0xffffffffu, s2, o);
    __syncthreads();
    if ((tid & 31) == 0) red[tid >> 5] = s2;
    __syncthreads();
    if (tid == 0) {
        float t = 0.f;
        #pragma unroll
        for (int i = 0; i < 8; i++) t += red[i];
        bc = t;
    }
    __syncthreads();
    float rstd = rsqrtf(bc * (1.f / DMODEL) + 1e-5f);
    float4 gg = ((const float4*)g)[tid];
    float4 bb = ((const float4*)b)[tid];
    float4 o4;
    o4.x = dx * rstd * gg.x + bb.x;
    o4.y = dy * rstd * gg.y + bb.y;
    o4.z = dz * rstd * gg.z + bb.z;
    o4.w = dw * rstd * gg.w + bb.w;
    ((float4*)(dst + (size_t)row * DMODEL))[tid] = o4;

    if (which == 0) {
        float am = fmaxf(fmaxf(fabsf(o4.x), fabsf(o4.y)), fmaxf(fabsf(o4.z), fabsf(o4.w)));
        #pragma unroll
        for (int o = 16; o >= 1; o >>= 1) am = fmaxf(am, __shfl_xor_sync(0xffffffffu, am, o));
        __syncthreads();
        if ((tid & 31) == 0) red[tid >> 5] = am;
        __syncthreads();
        if (tid == 0) {
            float t = 1e-20f;
            #pragma unroll
            for (int i = 0; i < 8; i++) t = fmaxf(t, red[i]);
            bc = t; g_sy[row] = t;
        }
        __syncthreads();
        float inv = 127.f / bc;
        char4 h4, l4;
        q_split(o4.x * inv, h4.x, l4.x);
        q_split(o4.y * inv, h4.y, l4.y);
        q_split(o4.z * inv, h4.z, l4.z);
        q_split(o4.w * inv, h4.w, l4.w);
        size_t idx = (size_t)row * DMODEL + tid * 4;
        *(char4*)((signed char*)(g_pool + OFF_YQH) + idx) = h4;
        *(char4*)((signed char*)(g_pool + OFF_YQL) + idx) = l4;
    }
}

// ================================ launch =====================================
extern "C" void kernel_launch(void* const* d_in, const int* in_sizes, int n_in,
                              void* d_out, int out_size)
{
    (void)in_sizes; (void)n_in; (void)out_size;
    const float* X   = (const float*)d_in[0];
    const float* Wq  = (const float*)d_in[1];
    const float* bq  = (const float*)d_in[2];
    const float* Wk  = (const float*)d_in[3];
    const float* bk  = (const float*)d_in[4];
    const float* Wv  = (const float*)d_in[5];
    const float* bv  = (const float*)d_in[6];
    const float* Wo  = (const float*)d_in[7];
    const float* bo  = (const float*)d_in[8];
    const float* l1g = (const float*)d_in[9];
    const float* l1b = (const float*)d_in[10];
    const float* W1  = (const float*)d_in[11];
    const float* b1  = (const float*)d_in[12];
    const float* W2  = (const float*)d_in[13];
    const float* b2  = (const float*)d_in[14];
    const float* l2g = (const float*)d_in[15];
    const float* l2b = (const float*)d_in[16];

    const int g8_smem = 2 * 30720;
    cudaFuncSetAttribute(gemm_i8<0>, cudaFuncAttributeMaxDynamicSharedMemorySize, g8_smem);
    cudaFuncSetAttribute(gemm_i8<1>, cudaFuncAttributeMaxDynamicSharedMemorySize, g8_smem);
    cudaFuncSetAttribute(gemm_i8<2>, cudaFuncAttributeMaxDynamicSharedMemorySize, g8_smem);
    cudaFuncSetAttribute(gemm_i8<3>, cudaFuncAttributeMaxDynamicSharedMemorySize, g8_smem);
    cudaFuncSetAttribute(gemm_i8<4>, cudaFuncAttributeMaxDynamicSharedMemorySize, g8_smem);
    cudaFuncSetAttribute(gemm_i8<5>, cudaFuncAttributeMaxDynamicSharedMemorySize, g8_smem);
    const int attn_smem = 30720;
    cudaFuncSetAttribute(attn_s8, cudaFuncAttributeMaxDynamicSharedMemorySize, attn_smem);

    dim3 thr(256);

    zero_scales<<<37, thr>>>();
    quant_rows<1024, 0><<<MB, thr>>>(X);
    wcolmax<<<dim3(4, 32),  thr>>>(Wq, 1024, 1024, 1, 0);
    wcolmax<<<dim3(4, 32),  thr>>>(Wk, 1024, 1024, 1, 1024);
    wcolmax<<<dim3(4, 32),  thr>>>(Wv, 1024, 1024, 1, 2048);
    wcolmax<<<dim3(4, 32),  thr>>>(Wo, 1024, 1024, 0, 3072);
    wcolmax<<<dim3(4, 32),  thr>>>(W2, 4096, 1024, 0, 4096);
    wcolmax<<<dim3(16, 32), thr>>>(W1, 1024, 4096, 0, 5120);
    conv_wq<<<dim3(32, 32),  thr>>>(Wq, 1024, 1024, 0, 0);
    conv_wq<<<dim3(32, 32),  thr>>>(Wk, 1024, 1024, 1, 1024);
    conv_wq<<<dim3(32, 32),  thr>>>(Wv, 1024, 1024, 2, 2048);
    conv_wq<<<dim3(32, 32),  thr>>>(Wo, 1024, 1024, 3, 3072);
    conv_wq<<<dim3(128, 32), thr>>>(W1, 1024, 4096, 4, 5120);
    conv_wq<<<dim3(32, 128), thr>>>(W2, 4096, 1024, 5, 4096);

    // QKV projections (1-limb) with fused per-bh absmax
    gemm_i8<0><<<dim3(16, 32), thr, g8_smem>>>(bq, nullptr);
    gemm_i8<1><<<dim3(16, 32), thr, g8_smem>>>(bk, nullptr);
    gemm_i8<2><<<dim3(16, 32), thr, g8_smem>>>(bv, nullptr);

    quant_qk2<<<8192, thr>>>();
    quant_vt<<<dim3(64, 2, 32), thr>>>();

    attn_s8<<<dim3(32, 32), dim3(128), attn_smem>>>();

    quant_rows<1024, 1><<<MB, thr>>>(nullptr);
    gemm_i8<3><<<dim3(16, 32), thr, g8_smem>>>(bo, X);
    ln_kernel<<<MB, thr>>>(l1g, l1b, nullptr, 0);

    gemm_i8<4><<<dim3(64, 32), thr, g8_smem>>>(b1, nullptr);
    quant_rows<4096, 2><<<MB, thr>>>(nullptr);
    gemm_i8<5><<<dim3(16, 32), thr, g8_smem>>>(b2, nullptr);
    ln_kernel<<<MB, thr>>>(l2g, l2b, (float*)d_out, 1);
}